// round 13
// baseline (speedup 1.0000x reference)
#include <cuda_runtime.h>
#include <cuda_fp16.h>
#include <math.h>
#include <stdint.h>

#define U_N 4000
#define P_N 4000
#define G_N 200
#define D   64
#define B_N 512
#define NUP (U_N + P_N)   // 8000
#define NGU (G_N + U_N)   // 4200
#define NGP (G_N + P_N)   // 4200
#define NTOT (NUP + NGU + NGP)

// ---------------- scratch (device globals; no allocation allowed) ----------
__device__ __align__(16) __half g_XT0[D * NUP];  // fp16 X^T, k-perm within 8-groups
__device__ __align__(16) __half g_XT1[D * NGU];
__device__ __align__(16) __half g_XT2[D * NGP];
__device__ __align__(16) float g_Rup[NUP * D];   // accumulators -> propagated
__device__ __align__(16) float g_Rgu[NGU * D];
__device__ __align__(16) float g_Rgp[NGP * D];
__device__ float g_deg[NTOT];
__device__ __align__(16) float g_uf[B_N * D];
__device__ __align__(16) float g_q [B_N * D];

// ---------------- merged init: transpose-build X^T(fp16) + zero R/deg -------
#define TP0 (250 * 2)
#define TP12 (132 * 2)
#define TPALL (TP0 + 2 * TP12)            // 764 transpose blocks
#define ZBLK ((NUP * (D / 4) + 255) / 256)  // 500 zero blocks
__global__ void init_and_transpose(const float* __restrict__ ue,
                                   const float* __restrict__ pe,
                                   const float* __restrict__ ge)
{
    int b = blockIdx.x;
    if (b >= TPALL) {
        // ---- zero path ----
        int i4 = (b - TPALL) * blockDim.x + threadIdx.x;
        const float4 z = make_float4(0.f, 0.f, 0.f, 0.f);
        if (i4 < NUP * (D / 4)) ((float4*)g_Rup)[i4] = z;
        if (i4 < NGU * (D / 4)) {
            ((float4*)g_Rgu)[i4] = z;
            ((float4*)g_Rgp)[i4] = z;
        }
        if (i4 < NTOT) g_deg[i4] = 0.f;
        return;
    }
    // ---- transpose path ----
    __shared__ float t[32][33];
    int prob, tile, n;
    __half* dst;
    if (b < TP0)            { prob = 0; tile = b;               n = NUP; dst = g_XT0; }
    else if (b < TP0 + TP12){ prob = 1; tile = b - TP0;         n = NGU; dst = g_XT1; }
    else                    { prob = 2; tile = b - TP0 - TP12;  n = NGP; dst = g_XT2; }

    const int rt = tile >> 1;
    const int ct = tile & 1;
    const int r0 = rt * 32;
    const int d0 = ct * 32;
    const int tx = threadIdx.x & 31;
    const int ty = threadIdx.x >> 5;

    #pragma unroll
    for (int j = 0; j < 4; j++) {
        int rr = ty + j * 8;
        int r  = r0 + rr;
        int d  = d0 + tx;
        float v = 0.f;
        if (r < n) {
            if (prob == 0) v = (r < U_N) ? ue[(size_t)r * D + d] : pe[(size_t)(r - U_N) * D + d];
            else if (prob == 1) v = (r < G_N) ? ge[(size_t)r * D + d] : ue[(size_t)(r - G_N) * D + d];
            else v = (r < G_N) ? ge[(size_t)r * D + d] : pe[(size_t)(r - G_N) * D + d];
        }
        t[rr][tx] = v;
    }
    __syncthreads();
    const int r = r0 + tx;
    if (r < n) {
        // k-permutation within 8-token group: phys = 2*(k&3) + ((k>>2)&1)
        const int rp = (r & ~7) + 2 * (r & 3) + ((r >> 2) & 1);
        #pragma unroll
        for (int j = 0; j < 4; j++) {
            int dd = ty + j * 8;
            dst[(size_t)(d0 + dd) * n + rp] = __float2half_rn(t[tx][dd]);
        }
    }
}

// ---------------- helpers ----------------------------------------------------
__device__ __forceinline__ unsigned smem_u32(const void* p)
{
    return (unsigned)__cvta_generic_to_shared(p);
}
__device__ __forceinline__ void mbar_init(unsigned mb, int count)
{
    asm volatile("mbarrier.init.shared.b64 [%0], %1;" :: "r"(mb), "r"(count) : "memory");
}
__device__ __forceinline__ void mbar_expect_tx(unsigned mb, unsigned bytes)
{
    asm volatile("mbarrier.arrive.expect_tx.shared.b64 _, [%0], %1;"
                 :: "r"(mb), "r"(bytes) : "memory");
}
__device__ __forceinline__ void mbar_wait(unsigned mb, int phase)
{
    asm volatile(
        "{\n\t"
        ".reg .pred P;\n\t"
        "W_%=:\n\t"
        "mbarrier.try_wait.parity.acquire.cta.shared::cta.b64 P, [%0], %1, 0x989680;\n\t"
        "@P bra D_%=;\n\t"
        "bra W_%=;\n\t"
        "D_%=:\n\t"
        "}"
        :: "r"(mb), "r"(phase) : "memory");
}
__device__ __forceinline__ void bulk_cp(unsigned smem_dst, const void* gmem_src,
                                        unsigned bytes, unsigned mb)
{
    asm volatile(
        "cp.async.bulk.shared::cluster.global.mbarrier::complete_tx::bytes [%0], [%1], %2, [%3];"
        :: "r"(smem_dst), "l"(gmem_src), "r"(bytes), "r"(mb) : "memory");
}
__device__ __forceinline__ void ldsm_x4(unsigned& r0, unsigned& r1,
                                        unsigned& r2, unsigned& r3, unsigned addr)
{
    asm volatile("ldmatrix.sync.aligned.m8n8.x4.shared.b16 {%0,%1,%2,%3}, [%4];"
                 : "=r"(r0), "=r"(r1), "=r"(r2), "=r"(r3) : "r"(addr));
}
__device__ __forceinline__ void ldsm_x2(unsigned& r0, unsigned& r1, unsigned addr)
{
    asm volatile("ldmatrix.sync.aligned.m8n8.x2.shared.b16 {%0,%1}, [%2];"
                 : "=r"(r0), "=r"(r1) : "r"(addr));
}
__device__ __forceinline__ void mma_tf32(
    float& c0, float& c1, float& c2, float& c3,
    unsigned a0, unsigned a1, unsigned a2, unsigned a3,
    unsigned b0, unsigned b1)
{
    asm volatile(
        "mma.sync.aligned.m16n8k8.row.col.f32.tf32.tf32.f32 "
        "{%0,%1,%2,%3}, {%4,%5,%6,%7}, {%8,%9}, {%0,%1,%2,%3};\n"
        : "+f"(c0), "+f"(c1), "+f"(c2), "+f"(c3)
        : "r"(a0), "r"(a1), "r"(a2), "r"(a3), "r"(b0), "r"(b1));
}
__device__ __forceinline__ float2 h2_to_f2(unsigned h)
{
    __half2 v = *reinterpret_cast<__half2*>(&h);
    return __half22float2(v);
}

// ---------------- propagation GEMM (R9 config + fp16 X) ---------------------
// R += A@X (tf32 MMA, atomics), deg += rowsum(A).
// A fp32 + X fp16 staged via cp.async.bulk; frags via ldmatrix b16.
#define BM 128
#define BKK 64
#define ASTR 68
#define XSTRH 72                    // halfs per X smem row
#define A_SZ (BM * ASTR)            // 8704 floats
#define X_SZF ((D * XSTRH) / 2)     // 2304 floats (4608 halfs)
#define STG (A_SZ + X_SZF)          // 11008 floats
#define G_SMEM_BYTES (2 * STG * 4)  // 88064 B

#define RT0 63
#define RT12 33
#define KS0 16
#define KS12 8
#define KPS0 8
#define KPS12 9
#define NB0 (RT0 * KS0)        // 1008
#define NB12 (RT12 * KS12)     // 264
#define NBLK (NB0 + 2 * NB12)  // 1536

__device__ __forceinline__ void issue_stage(
    float* Abuf, __half* Xbuf, unsigned mb,
    const float* __restrict__ A, const __half* __restrict__ XT,
    int n, int rowBase, int k0, int kEnd, int tid)
{
    const int kChunk = min(BKK, kEnd - k0);
    const unsigned kBytesA = (unsigned)kChunk * 4u;
    const unsigned kBytesX = (unsigned)kChunk * 2u;
    if (tid == 0) {
        int nA = min(BM, n - rowBase);
        mbar_expect_tx(mb, (unsigned)nA * kBytesA + (unsigned)D * kBytesX);
    }
    {
        int gr = rowBase + tid;
        if (gr < n)
            bulk_cp(smem_u32(Abuf + tid * ASTR), A + (size_t)gr * n + k0, kBytesA, mb);
    }
    if (tid < D)
        bulk_cp(smem_u32(Xbuf + tid * XSTRH), XT + (size_t)tid * n + k0, kBytesX, mb);
}

extern "C" __global__ void __launch_bounds__(128, 2)
gemm_all(const float* __restrict__ A0, const float* __restrict__ A1,
         const float* __restrict__ A2,
         const __half* __restrict__ XT0, const __half* __restrict__ XT1,
         const __half* __restrict__ XT2,
         float* __restrict__ R0, float* __restrict__ R1, float* __restrict__ R2,
         float* __restrict__ degAll)
{
    extern __shared__ float dyn[];
    __shared__ uint64_t mbar[2];

    float*  AbufS[2] = { dyn,                   dyn + STG };
    __half* XbufS[2] = { (__half*)(dyn + A_SZ), (__half*)(dyn + STG + A_SZ) };

    const int tid  = threadIdx.x;
    const int lane = tid & 31;
    const int warp = tid >> 5;
    const int rq   = lane >> 2;
    const int kc   = lane & 3;
    const int wrow = warp * 32;

    const unsigned aLaneOff =
        (unsigned)(((lane & 7) + ((lane >> 3) & 1) * 8 + wrow) * ASTR) * 4u
        + (unsigned)(lane >> 4) * 16u;
    // fp16 X tiles: row = (lane&7) + d-half((lane>>3)&1)*8 ; ks-half (lane>>4) adds 16B
    const unsigned xLaneOffH =
        (unsigned)(((lane & 7) + ((lane >> 3) & 1) * 8) * XSTRH) * 2u
        + (unsigned)(lane >> 4) * 16u;

    // ---- map block -> (problem, rowTile, ksplit) ----
    const float* A; const __half* XT; float *R, *deg;
    int n, kIters, kps, rowTile, split;
    int b = blockIdx.x;
    if (b < NB0) {
        A = A0; XT = XT0; R = R0; deg = degAll; n = NUP; kIters = 125; kps = KPS0;
        rowTile = b % RT0; split = b / RT0;
    } else {
        int idx = b - NB0;
        if (idx < NB12) { A = A1; XT = XT1; R = R1; deg = degAll + NUP;       n = NGU; }
        else            { A = A2; XT = XT2; R = R2; deg = degAll + NUP + NGU; n = NGP; idx -= NB12; }
        kIters = 66; kps = KPS12;
        rowTile = idx % RT12; split = idx / RT12;
    }

    const int rowBase = rowTile * BM;
    const int itStart = split * kps;
    const int itEnd   = min(kIters, itStart + kps);
    const int nIt     = itEnd - itStart;
    if (nIt <= 0) return;
    const int kEnd = min(n, itEnd * BKK);

    if (tid == 0) { mbar_init(smem_u32(&mbar[0]), 1); mbar_init(smem_u32(&mbar[1]), 1); }
    __syncthreads();

    issue_stage(AbufS[0], XbufS[0], smem_u32(&mbar[0]), A, XT, n, rowBase,
                itStart * BKK, kEnd, tid);

    float c0[8][4], c1[8][4];
    #pragma unroll
    for (int nt = 0; nt < 8; nt++)
        #pragma unroll
        for (int j = 0; j < 4; j++) { c0[nt][j] = 0.f; c1[nt][j] = 0.f; }
    float dacc[2][2] = {{0.f, 0.f}, {0.f, 0.f}};

    const int r00 = rowBase + wrow + rq;
    const int r10 = r00 + 16;
    int ph0 = 0, ph1 = 0;

    for (int i = 0; i < nIt; i++) {
        const int cur = i & 1;
        const int k0  = (itStart + i) * BKK;

        if (i + 1 < nIt)
            issue_stage(AbufS[cur ^ 1], XbufS[cur ^ 1], smem_u32(&mbar[cur ^ 1]),
                        A, XT, n, rowBase, k0 + BKK, kEnd, tid);

        if (cur == 0) { mbar_wait(smem_u32(&mbar[0]), ph0); ph0 ^= 1; }
        else          { mbar_wait(smem_u32(&mbar[1]), ph1); ph1 ^= 1; }

        const unsigned aBase  = smem_u32(AbufS[cur]) + aLaneOff;
        const unsigned xBaseH = smem_u32(XbufS[cur]) + xLaneOffH;
        const int kSteps = min(BKK, kEnd - k0) >> 3;

        int ks = 0;
        #pragma unroll 4
        for (; ks + 1 < kSteps; ks += 2) {
            const unsigned kbB0 = (unsigned)(ks * 8) * 4u;
            const unsigned kbB1 = kbB0 + 32u;
            unsigned a00[4], a01[4], a10[4], a11[4];
            ldsm_x4(a00[0], a00[1], a00[2], a00[3], aBase + kbB0);
            ldsm_x4(a10[0], a10[1], a10[2], a10[3], aBase + 16u * ASTR * 4u + kbB0);
            ldsm_x4(a01[0], a01[1], a01[2], a01[3], aBase + kbB1);
            ldsm_x4(a11[0], a11[1], a11[2], a11[3], aBase + 16u * ASTR * 4u + kbB1);
            dacc[0][0] += __uint_as_float(a00[0]) + __uint_as_float(a00[2])
                        + __uint_as_float(a01[0]) + __uint_as_float(a01[2]);
            dacc[0][1] += __uint_as_float(a00[1]) + __uint_as_float(a00[3])
                        + __uint_as_float(a01[1]) + __uint_as_float(a01[3]);
            dacc[1][0] += __uint_as_float(a10[0]) + __uint_as_float(a10[2])
                        + __uint_as_float(a11[0]) + __uint_as_float(a11[2]);
            dacc[1][1] += __uint_as_float(a10[1]) + __uint_as_float(a10[3])
                        + __uint_as_float(a11[1]) + __uint_as_float(a11[3]);
            #pragma unroll
            for (int p = 0; p < 4; p++) {
                unsigned h0, h1, h2, h3;
                ldsm_x4(h0, h1, h2, h3,
                        xBaseH + (unsigned)(p * 16 * XSTRH) * 2u + (unsigned)(ks * 16));
                float2 f0 = h2_to_f2(h0);   // (nt=2p,   ks)
                float2 f1 = h2_to_f2(h1);   // (nt=2p+1, ks)
                float2 f2 = h2_to_f2(h2);   // (nt=2p,   ks+1)
                float2 f3 = h2_to_f2(h3);   // (nt=2p+1, ks+1)
                mma_tf32(c0[2*p][0], c0[2*p][1], c0[2*p][2], c0[2*p][3],
                         a00[0], a00[1], a00[2], a00[3],
                         __float_as_uint(f0.x), __float_as_uint(f0.y));
                mma_tf32(c0[2*p+1][0], c0[2*p+1][1], c0[2*p+1][2], c0[2*p+1][3],
                         a00[0], a00[1], a00[2], a00[3],
                         __float_as_uint(f1.x), __float_as_uint(f1.y));
                mma_tf32(c1[2*p][0], c1[2*p][1], c1[2*p][2], c1[2*p][3],
                         a10[0], a10[1], a10[2], a10[3],
                         __float_as_uint(f0.x), __float_as_uint(f0.y));
                mma_tf32(c1[2*p+1][0], c1[2*p+1][1], c1[2*p+1][2], c1[2*p+1][3],
                         a10[0], a10[1], a10[2], a10[3],
                         __float_as_uint(f1.x), __float_as_uint(f1.y));
                mma_tf32(c0[2*p][0], c0[2*p][1], c0[2*p][2], c0[2*p][3],
                         a01[0], a01[1], a01[2], a01[3],
                         __float_as_uint(f2.x), __float_as_uint(f2.y));
                mma_tf32(c0[2*p+1][0], c0[2*p+1][1], c0[2*p+1][2], c0[2*p+1][3],
                         a01[0], a01[1], a01[2], a01[3],
                         __float_as_uint(f3.x), __float_as_uint(f3.y));
                mma_tf32(c1[2*p][0], c1[2*p][1], c1[2*p][2], c1[2*p][3],
                         a11[0], a11[1], a11[2], a11[3],
                         __float_as_uint(f2.x), __float_as_uint(f2.y));
                mma_tf32(c1[2*p+1][0], c1[2*p+1][1], c1[2*p+1][2], c1[2*p+1][3],
                         a11[0], a11[1], a11[2], a11[3],
                         __float_as_uint(f3.x), __float_as_uint(f3.y));
            }
        }
        if (ks < kSteps) {   // odd tail (last split of problems 1/2 only)
            const unsigned kbB = (unsigned)(ks * 8) * 4u;
            unsigned a0[4], a1[4];
            ldsm_x4(a0[0], a0[1], a0[2], a0[3], aBase + kbB);
            ldsm_x4(a1[0], a1[1], a1[2], a1[3], aBase + 16u * ASTR * 4u + kbB);
            dacc[0][0] += __uint_as_float(a0[0]) + __uint_as_float(a0[2]);
            dacc[0][1] += __uint_as_float(a0[1]) + __uint_as_float(a0[3]);
            dacc[1][0] += __uint_as_float(a1[0]) + __uint_as_float(a1[2]);
            dacc[1][1] += __uint_as_float(a1[1]) + __uint_as_float(a1[3]);
            #pragma unroll
            for (int p = 0; p < 4; p++) {
                unsigned h0, h1;
                ldsm_x2(h0, h1,
                        xBaseH + (unsigned)(p * 16 * XSTRH) * 2u + (unsigned)(ks * 16));
                float2 f0 = h2_to_f2(h0);
                float2 f1 = h2_to_f2(h1);
                mma_tf32(c0[2*p][0], c0[2*p][1], c0[2*p][2], c0[2*p][3],
                         a0[0], a0[1], a0[2], a0[3],
                         __float_as_uint(f0.x), __float_as_uint(f0.y));
                mma_tf32(c0[2*p+1][0], c0[2*p+1][1], c0[2*p+1][2], c0[2*p+1][3],
                         a0[0], a0[1], a0[2], a0[3],
                         __float_as_uint(f1.x), __float_as_uint(f1.y));
                mma_tf32(c1[2*p][0], c1[2*p][1], c1[2*p][2], c1[2*p][3],
                         a1[0], a1[1], a1[2], a1[3],
                         __float_as_uint(f0.x), __float_as_uint(f0.y));
                mma_tf32(c1[2*p+1][0], c1[2*p+1][1], c1[2*p+1][2], c1[2*p+1][3],
                         a1[0], a1[1], a1[2], a1[3],
                         __float_as_uint(f1.x), __float_as_uint(f1.y));
            }
        }
        __syncthreads();
    }

    // ---- deg: reduce over the 4 kc lanes, one atomic per row ----
    #pragma unroll
    for (int mt = 0; mt < 2; mt++) {
        float v0 = dacc[mt][0], v1 = dacc[mt][1];
        v0 += __shfl_xor_sync(0xffffffffu, v0, 1);
        v0 += __shfl_xor_sync(0xffffffffu, v0, 2);
        v1 += __shfl_xor_sync(0xffffffffu, v1, 1);
        v1 += __shfl_xor_sync(0xffffffffu, v1, 2);
        int r = (mt == 0) ? r00 : r10;
        if (kc == 0) {
            if (r < n)     atomicAdd(&deg[r], v0);
            if (r + 8 < n) atomicAdd(&deg[r + 8], v1);
        }
    }

    // ---- accumulate split-K partials (L2-resident R, atomics are cheap) ----
    const int ccBase = kc * 2;
    #pragma unroll
    for (int mt = 0; mt < 2; mt++) {
        const int r = (mt == 0) ? r00 : r10;
        float (*cc)[4] = (mt == 0) ? c0 : c1;
        #pragma unroll
        for (int nt = 0; nt < 8; nt++) {
            int col = nt * 8 + ccBase;
            if (r < n) {
                atomicAdd(&R[r * D + col],     cc[nt][0]);
                atomicAdd(&R[r * D + col + 1], cc[nt][1]);
            }
            if (r + 8 < n) {
                atomicAdd(&R[(r + 8) * D + col],     cc[nt][2]);
                atomicAdd(&R[(r + 8) * D + col + 1], cc[nt][3]);
            }
        }
    }
}

// ---------------- epilogue: R = (X + R/max(deg,1e-8)) * 0.5 (in place) ------
__global__ void epilogue_all(const float4* __restrict__ ue,
                             const float4* __restrict__ pe,
                             const float4* __restrict__ ge)
{
    int i4 = blockIdx.x * blockDim.x + threadIdx.x;
    if (i4 >= NTOT * (D / 4)) return;
    int row = i4 >> 4;
    int c4  = i4 & 15;
    float d = fmaxf(g_deg[row], 1e-8f);

    float4 x;
    float4* Rp;
    if (row < NUP) {
        x = (row < U_N) ? ue[(size_t)row * 16 + c4] : pe[(size_t)(row - U_N) * 16 + c4];
        Rp = reinterpret_cast<float4*>(g_Rup) + i4;
    } else if (row < NUP + NGU) {
        int lrow = row - NUP;
        x = (lrow < G_N) ? ge[(size_t)lrow * 16 + c4] : ue[(size_t)(lrow - G_N) * 16 + c4];
        Rp = reinterpret_cast<float4*>(g_Rgu) + (lrow * 16 + c4);
    } else {
        int lrow = row - NUP - NGU;
        x = (lrow < G_N) ? ge[(size_t)lrow * 16 + c4] : pe[(size_t)(lrow - G_N) * 16 + c4];
        Rp = reinterpret_cast<float4*>(g_Rgp) + (lrow * 16 + c4);
    }
    float4 r = *Rp;
    r.x = (x.x + r.x / d) * 0.5f;
    r.y = (x.y + r.y / d) * 0.5f;
    r.z = (x.z + r.z / d) * 0.5f;
    r.w = (x.w + r.w / d) * 0.5f;
    *Rp = r;
}

// ---------------- user_feat gather + q = uf @ W (4 users / 256-thr block) ---
__global__ void __launch_bounds__(256)
uf_q_kernel(const int* __restrict__ uids,
            const float* __restrict__ W,
            float* __restrict__ out_uf)
{
    __shared__ float sh[4][D];
    int u  = threadIdx.x >> 6;
    int d  = threadIdx.x & 63;
    int b  = blockIdx.x * 4 + u;
    int uid = uids[b];
    float v = 0.5f * (g_Rup[uid * D + d] + g_Rgu[(G_N + uid) * D + d]);
    sh[u][d] = v;
    g_uf[b * D + d] = v;
    out_uf[b * D + d] = v;
    __syncthreads();
    float acc = 0.f;
    #pragma unroll
    for (int k = 0; k < D; k++) acc += sh[u][k] * W[k * D + d];
    g_q[b * D + d] = acc;
}

// ---------------- score kernel: diff form, 3-term compensated (7 MMAs) ------
#define SST 72
#define S_SMEM_BYTES (4 * 64 * SST * 4)

__device__ __forceinline__ void split13(float x, unsigned& hi, unsigned& lo)
{
    unsigned h = __float_as_uint(x) & 0xFFFFE000u;
    hi = h;
    lo = __float_as_uint(x - __uint_as_float(h));
}

extern "C" __global__ void __launch_bounds__(256, 2)
score_all(float* __restrict__ scores)
{
    extern __shared__ float smem[];
    float* Qs  = smem;
    float* Us  = Qs  + 64 * SST;
    float* I1s = Us  + 64 * SST;
    float* IDs = I1s + 64 * SST;

    const int tid   = threadIdx.x;
    const int lane  = tid & 31;
    const int warp  = tid >> 5;
    const int warpB = warp >> 1;
    const int warpP = warp & 1;
    const int rq    = lane >> 2;
    const int kc    = lane & 3;
    const int ub    = blockIdx.y * 64;
    const int pb    = blockIdx.x * 64;

    #pragma unroll
    for (int it = 0; it < 4; it++) {
        int slot = tid + it * 256;
        int r  = slot >> 4;
        int c4 = (slot & 15) << 2;
        float4 q = *reinterpret_cast<const float4*>(&g_q [(size_t)(ub + r) * D + c4]);
        float4 u = *reinterpret_cast<const float4*>(&g_uf[(size_t)(ub + r) * D + c4]);
        *reinterpret_cast<float4*>(&Qs[r * SST + c4]) = q;
        *reinterpret_cast<float4*>(&Us[r * SST + c4]) = u;
        int gp = pb + r;
        float4 v0 = make_float4(0.f, 0.f, 0.f, 0.f), v1 = v0;
        if (gp < P_N) {
            v0 = *reinterpret_cast<const float4*>(&g_Rup[(size_t)(U_N + gp) * D + c4]);
            v1 = *reinterpret_cast<const float4*>(&g_Rgp[(size_t)(G_N + gp) * D + c4]);
        }
        *reinterpret_cast<float4*>(&I1s[r * SST + c4]) = v1;
        float4 dv = make_float4(v0.x - v1.x, v0.y - v1.y, v0.z - v1.z, v0.w - v1.w);
        *reinterpret_cast<float4*>(&IDs[r * SST + c4]) = dv;
    }
    __syncthreads();

    float z[4][4] = {}, dd[4][4] = {}, d1[4][4] = {};
    const int ar = warpB * 16 + rq;

    #pragma unroll
    for (int ks = 0; ks < 8; ks++) {
        int kb = ks * 8;
        unsigned aq[4];
        float uf[4];
        aq[0] = __float_as_uint(Qs[ar * SST + kb + kc]);
        aq[1] = __float_as_uint(Qs[(ar + 8) * SST + kb + kc]);
        aq[2] = __float_as_uint(Qs[ar * SST + kb + kc + 4]);
        aq[3] = __float_as_uint(Qs[(ar + 8) * SST + kb + kc + 4]);
        uf[0] = Us[ar * SST + kb + kc];
        uf[1] = Us[(ar + 8) * SST + kb + kc];
        uf[2] = Us[ar * SST + kb + kc + 4];
        uf[3] = Us[(ar + 8) * SST + kb + kc + 4];
        unsigned uh[4], ul[4];
        #pragma unroll
        for (int j = 0; j < 4; j++) split13(uf[j], uh[j], ul[j]);

        #pragma unroll
        for (int nt = 0; nt < 4; nt++) {
            int col = warpP * 32 + nt * 8 + rq;
            float bd0 = IDs[col * SST + kb + kc];
            float bd1 = IDs[col * SST + kb + kc + 4];
            float b10 = I1s[col * SST + kb + kc];
            float b11 = I1s[col * SST + kb + kc + 4];
            unsigned hd0, ld0, hd1, ld1, h10, l10, h11, l11;
            split13(bd0, hd0, ld0); split13(bd1, hd1, ld1);
            split13(b10, h10, l10); split13(b11, h11, l11);

            mma_tf32(z[nt][0], z[nt][1], z[nt][2], z[nt][3],
                     aq[0], aq[1], aq[2], aq[3], hd0, hd1);
            mma_tf32(dd[nt][0], dd[nt][1], dd[nt][2], dd[nt][3],
                     uh[0], uh[1], uh[2], uh[3], hd0, hd1);
            mma_tf32(dd[nt][0], dd[nt][1], dd[nt][2], dd[nt][3],
                     uh[0], uh[1], uh[2], uh[3], ld0, ld1);
            mma_tf32(dd[nt][0], dd[nt][1], dd[nt][2], dd[nt][3],
                     ul[0], ul[1], ul[2], ul[3], hd0, hd1);
            mma_tf32(d1[nt][0], d1[nt][1], d1[nt][2], d1[nt][3],
                     uh[0], uh[1], uh[2], uh[3], h10, h11);
            mma_tf32(d1[nt][0], d1[nt][1], d1[nt][2], d1[nt][3],
                     uh[0], uh[1], uh[2], uh[3], l10, l11);
            mma_tf32(d1[nt][0], d1[nt][1], d1[nt][2], d1[nt][3],
                     ul[0], ul[1], ul[2], ul[3], h10, h11);
        }
    }

    const float scale = 0.125f;
    #pragma unroll
    for (int nt = 0; nt < 4; nt++) {
        #pragma unroll
        for (int j = 0; j < 4; j++) {
            int r = ub + warpB * 16 + rq + ((j >= 2) ? 8 : 0);
            int p = pb + warpP * 32 + nt * 8 + kc * 2 + (j & 1);
            if (p < P_N) {
                float a0 = 1.f / (1.f + expf(-z[nt][j] * scale));
                scores[(size_t)r * P_N + p] = d1[nt][j] + a0 * dd[nt][j];
            }
        }
    }
}

// ---------------- launch -----------------------------------------------------
extern "C" void kernel_launch(void* const* d_in, const int* in_sizes, int n_in,
                              void* d_out, int out_size)
{
    const float* A_up = (const float*)d_in[0];
    const float* A_gu = (const float*)d_in[1];
    const float* A_gp = (const float*)d_in[2];
    const float* ue   = (const float*)d_in[3];
    const float* pe   = (const float*)d_in[4];
    const float* ge   = (const float*)d_in[5];
    const float* W    = (const float*)d_in[6];
    const int*   uids = (const int*)d_in[7];
    float* out = (float*)d_out;

    __half *pXT0, *pXT1, *pXT2;
    float *pRup, *pRgu, *pRgp, *pdeg;
    cudaGetSymbolAddress((void**)&pXT0, g_XT0);
    cudaGetSymbolAddress((void**)&pXT1, g_XT1);
    cudaGetSymbolAddress((void**)&pXT2, g_XT2);
    cudaGetSymbolAddress((void**)&pRup, g_Rup);
    cudaGetSymbolAddress((void**)&pRgu, g_Rgu);
    cudaGetSymbolAddress((void**)&pRgp, g_Rgp);
    cudaGetSymbolAddress((void**)&pdeg, g_deg);

    cudaFuncSetAttribute(gemm_all,  cudaFuncAttributeMaxDynamicSharedMemorySize, G_SMEM_BYTES);
    cudaFuncSetAttribute(score_all, cudaFuncAttributeMaxDynamicSharedMemorySize, S_SMEM_BYTES);

    init_and_transpose<<<TPALL + ZBLK, 256>>>(ue, pe, ge);

    gemm_all<<<NBLK, 128, G_SMEM_BYTES>>>(A_up, A_gu, A_gp,
                                          pXT0, pXT1, pXT2,
                                          pRup, pRgu, pRgp, pdeg);

    epilogue_all<<<(NTOT * (D / 4) + 255) / 256, 256>>>(
        (const float4*)ue, (const float4*)pe, (const float4*)ge);

    uf_q_kernel<<<B_N / 4, 256>>>(uids, W, out + (size_t)B_N * P_N);

    dim3 sg((P_N + 63) / 64, B_N / 64);
    score_all<<<sg, 256, S_SMEM_BYTES>>>(out);
}

// round 14
// speedup vs baseline: 1.1036x; 1.1036x over previous
#include <cuda_runtime.h>
#include <math.h>
#include <stdint.h>

#define U_N 4000
#define P_N 4000
#define G_N 200
#define D   64
#define B_N 512
#define NUP (U_N + P_N)   // 8000
#define NGU (G_N + U_N)   // 4200
#define NGP (G_N + P_N)   // 4200
#define NTOT (NUP + NGU + NGP)

// ---------------- scratch (device globals; no allocation allowed) ----------
__device__ __align__(16) float g_XT0[D * NUP];   // transposed X (N-major rows)
__device__ __align__(16) float g_XT1[D * NGU];
__device__ __align__(16) float g_XT2[D * NGP];
__device__ __align__(16) float g_Rup[NUP * D];   // accumulators -> propagated
__device__ __align__(16) float g_Rgu[NGU * D];
__device__ __align__(16) float g_Rgp[NGP * D];
__device__ float g_deg[NTOT];
__device__ __align__(16) float g_uf[B_N * D];
__device__ __align__(16) float g_q [B_N * D];

// ---------------- merged init: transpose-build X^T + zero R/deg -------------
#define TP0 (250 * 2)
#define TP12 (132 * 2)
#define TPALL (TP0 + 2 * TP12)              // 764 transpose blocks
#define ZBLK ((NUP * (D / 4) + 255) / 256)  // 500 zero blocks
__global__ void init_and_transpose(const float* __restrict__ ue,
                                   const float* __restrict__ pe,
                                   const float* __restrict__ ge)
{
    int b = blockIdx.x;
    if (b >= TPALL) {
        int i4 = (b - TPALL) * blockDim.x + threadIdx.x;
        const float4 z = make_float4(0.f, 0.f, 0.f, 0.f);
        if (i4 < NUP * (D / 4)) ((float4*)g_Rup)[i4] = z;
        if (i4 < NGU * (D / 4)) {
            ((float4*)g_Rgu)[i4] = z;
            ((float4*)g_Rgp)[i4] = z;
        }
        if (i4 < NTOT) g_deg[i4] = 0.f;
        return;
    }
    __shared__ float t[32][33];
    int prob, tile, n;
    float* dst;
    if (b < TP0)            { prob = 0; tile = b;               n = NUP; dst = g_XT0; }
    else if (b < TP0 + TP12){ prob = 1; tile = b - TP0;         n = NGU; dst = g_XT1; }
    else                    { prob = 2; tile = b - TP0 - TP12;  n = NGP; dst = g_XT2; }

    const int rt = tile >> 1;
    const int ct = tile & 1;
    const int r0 = rt * 32;
    const int d0 = ct * 32;
    const int tx = threadIdx.x & 31;
    const int ty = threadIdx.x >> 5;

    #pragma unroll
    for (int j = 0; j < 4; j++) {
        int rr = ty + j * 8;
        int r  = r0 + rr;
        int d  = d0 + tx;
        float v = 0.f;
        if (r < n) {
            if (prob == 0) v = (r < U_N) ? ue[(size_t)r * D + d] : pe[(size_t)(r - U_N) * D + d];
            else if (prob == 1) v = (r < G_N) ? ge[(size_t)r * D + d] : ue[(size_t)(r - G_N) * D + d];
            else v = (r < G_N) ? ge[(size_t)r * D + d] : pe[(size_t)(r - G_N) * D + d];
        }
        t[rr][tx] = v;
    }
    __syncthreads();
    const int r = r0 + tx;
    if (r < n) {
        #pragma unroll
        for (int j = 0; j < 4; j++) {
            int dd = ty + j * 8;
            dst[(size_t)(d0 + dd) * n + r] = t[tx][dd];
        }
    }
}

// ---------------- helpers ----------------------------------------------------
__device__ __forceinline__ unsigned smem_u32(const void* p)
{
    return (unsigned)__cvta_generic_to_shared(p);
}
__device__ __forceinline__ void mbar_init(unsigned mb, int count)
{
    asm volatile("mbarrier.init.shared.b64 [%0], %1;" :: "r"(mb), "r"(count) : "memory");
}
__device__ __forceinline__ void mbar_expect_tx(unsigned mb, unsigned bytes)
{
    asm volatile("mbarrier.arrive.expect_tx.shared.b64 _, [%0], %1;"
                 :: "r"(mb), "r"(bytes) : "memory");
}
__device__ __forceinline__ void mbar_wait(unsigned mb, int phase)
{
    asm volatile(
        "{\n\t"
        ".reg .pred P;\n\t"
        "W_%=:\n\t"
        "mbarrier.try_wait.parity.acquire.cta.shared::cta.b64 P, [%0], %1, 0x989680;\n\t"
        "@P bra D_%=;\n\t"
        "bra W_%=;\n\t"
        "D_%=:\n\t"
        "}"
        :: "r"(mb), "r"(phase) : "memory");
}
__device__ __forceinline__ void bulk_cp(unsigned smem_dst, const void* gmem_src,
                                        unsigned bytes, unsigned mb)
{
    asm volatile(
        "cp.async.bulk.shared::cluster.global.mbarrier::complete_tx::bytes [%0], [%1], %2, [%3];"
        :: "r"(smem_dst), "l"(gmem_src), "r"(bytes), "r"(mb) : "memory");
}
__device__ __forceinline__ void ldsm_x4(unsigned& r0, unsigned& r1,
                                        unsigned& r2, unsigned& r3, unsigned addr)
{
    asm volatile("ldmatrix.sync.aligned.m8n8.x4.shared.b16 {%0,%1,%2,%3}, [%4];"
                 : "=r"(r0), "=r"(r1), "=r"(r2), "=r"(r3) : "r"(addr));
}
__device__ __forceinline__ void mma_tf32(
    float& c0, float& c1, float& c2, float& c3,
    unsigned a0, unsigned a1, unsigned a2, unsigned a3,
    unsigned b0, unsigned b1)
{
    asm volatile(
        "mma.sync.aligned.m16n8k8.row.col.f32.tf32.tf32.f32 "
        "{%0,%1,%2,%3}, {%4,%5,%6,%7}, {%8,%9}, {%0,%1,%2,%3};\n"
        : "+f"(c0), "+f"(c1), "+f"(c2), "+f"(c3)
        : "r"(a0), "r"(a1), "r"(a2), "r"(a3), "r"(b0), "r"(b1));
}
// round-to-nearest tf32 split: hi RN-rounded, lo = x - hi (|lo| halved vs trunc)
__device__ __forceinline__ void split_rn(float x, unsigned& hi, unsigned& lo)
{
    unsigned h;
    asm("cvt.rn.tf32.f32 %0, %1;" : "=r"(h) : "f"(x));
    hi = h;
    lo = __float_as_uint(x - __uint_as_float(h));
}

// ---------------- propagation GEMM (R9 config — best measured) --------------
#define BM 128
#define BKK 64
#define ASTR 68
#define XSTR 68
#define A_SZ (BM * ASTR)
#define X_SZ (D * XSTR)
#define STG (A_SZ + X_SZ)
#define G_SMEM_BYTES (2 * STG * 4)

#define RT0 63
#define RT12 33
#define KS0 16
#define KS12 8
#define KPS0 8
#define KPS12 9
#define NB0 (RT0 * KS0)        // 1008
#define NB12 (RT12 * KS12)     // 264
#define NBLK (NB0 + 2 * NB12)  // 1536

__device__ __forceinline__ void issue_stage(
    float* Abuf, float* Xbuf, unsigned mb,
    const float* __restrict__ A, const float* __restrict__ XT,
    int n, int rowBase, int k0, int kEnd, int tid)
{
    const int kChunk = min(BKK, kEnd - k0);
    const unsigned kBytes = (unsigned)kChunk * 4u;
    if (tid == 0) {
        int nA = min(BM, n - rowBase);
        mbar_expect_tx(mb, (unsigned)nA * kBytes + (unsigned)D * kBytes);
    }
    {
        int gr = rowBase + tid;
        if (gr < n)
            bulk_cp(smem_u32(Abuf + tid * ASTR), A + (size_t)gr * n + k0, kBytes, mb);
    }
    if (tid < D)
        bulk_cp(smem_u32(Xbuf + tid * XSTR), XT + (size_t)tid * n + k0, kBytes, mb);
}

extern "C" __global__ void __launch_bounds__(128, 2)
gemm_all(const float* __restrict__ A0, const float* __restrict__ A1,
         const float* __restrict__ A2,
         const float* __restrict__ XT0, const float* __restrict__ XT1,
         const float* __restrict__ XT2,
         float* __restrict__ R0, float* __restrict__ R1, float* __restrict__ R2,
         float* __restrict__ degAll)
{
    extern __shared__ float dyn[];
    __shared__ uint64_t mbar[2];

    float* AbufS[2] = { dyn,        dyn + STG };
    float* XbufS[2] = { dyn + A_SZ, dyn + STG + A_SZ };

    const int tid  = threadIdx.x;
    const int lane = tid & 31;
    const int warp = tid >> 5;
    const int rq   = lane >> 2;
    const int kc   = lane & 3;
    const int wrow = warp * 32;

    const unsigned aLaneOff =
        (unsigned)(((lane & 7) + ((lane >> 3) & 1) * 8 + wrow) * ASTR) * 4u
        + (unsigned)(lane >> 4) * 16u;
    const unsigned xLaneOff =
        (unsigned)(((lane & 7) + (lane >> 4) * 8) * XSTR) * 4u
        + (unsigned)((lane >> 3) & 1) * 16u;

    // ---- map block -> (problem, rowTile, ksplit) ----
    const float *A, *XT; float *R, *deg;
    int n, kIters, kps, rowTile, split;
    int b = blockIdx.x;
    if (b < NB0) {
        A = A0; XT = XT0; R = R0; deg = degAll; n = NUP; kIters = 125; kps = KPS0;
        rowTile = b % RT0; split = b / RT0;
    } else {
        int idx = b - NB0;
        if (idx < NB12) { A = A1; XT = XT1; R = R1; deg = degAll + NUP;       n = NGU; }
        else            { A = A2; XT = XT2; R = R2; deg = degAll + NUP + NGU; n = NGP; idx -= NB12; }
        kIters = 66; kps = KPS12;
        rowTile = idx % RT12; split = idx / RT12;
    }

    const int rowBase = rowTile * BM;
    const int itStart = split * kps;
    const int itEnd   = min(kIters, itStart + kps);
    const int nIt     = itEnd - itStart;
    if (nIt <= 0) return;
    const int kEnd = min(n, itEnd * BKK);

    if (tid == 0) { mbar_init(smem_u32(&mbar[0]), 1); mbar_init(smem_u32(&mbar[1]), 1); }
    __syncthreads();

    issue_stage(AbufS[0], XbufS[0], smem_u32(&mbar[0]), A, XT, n, rowBase,
                itStart * BKK, kEnd, tid);

    float c0[8][4], c1[8][4];
    #pragma unroll
    for (int nt = 0; nt < 8; nt++)
        #pragma unroll
        for (int j = 0; j < 4; j++) { c0[nt][j] = 0.f; c1[nt][j] = 0.f; }
    float dacc[2][2] = {{0.f, 0.f}, {0.f, 0.f}};

    const int r00 = rowBase + wrow + rq;
    const int r10 = r00 + 16;
    int ph0 = 0, ph1 = 0;

    for (int i = 0; i < nIt; i++) {
        const int cur = i & 1;
        const int k0  = (itStart + i) * BKK;

        if (i + 1 < nIt)
            issue_stage(AbufS[cur ^ 1], XbufS[cur ^ 1], smem_u32(&mbar[cur ^ 1]),
                        A, XT, n, rowBase, k0 + BKK, kEnd, tid);

        if (cur == 0) { mbar_wait(smem_u32(&mbar[0]), ph0); ph0 ^= 1; }
        else          { mbar_wait(smem_u32(&mbar[1]), ph1); ph1 ^= 1; }

        const unsigned aBase = smem_u32(AbufS[cur]) + aLaneOff;
        const unsigned xBase = smem_u32(XbufS[cur]) + xLaneOff;
        const int kSteps = min(BKK, kEnd - k0) >> 3;

        #pragma unroll 8
        for (int ks = 0; ks < kSteps; ks++) {
            const unsigned kbB = (unsigned)(ks * 8) * 4u;
            unsigned a0[4], a1[4];
            ldsm_x4(a0[0], a0[1], a0[2], a0[3], aBase + kbB);
            ldsm_x4(a1[0], a1[1], a1[2], a1[3], aBase + 16u * ASTR * 4u + kbB);
            dacc[0][0] += __uint_as_float(a0[0]) + __uint_as_float(a0[2]);
            dacc[0][1] += __uint_as_float(a0[1]) + __uint_as_float(a0[3]);
            dacc[1][0] += __uint_as_float(a1[0]) + __uint_as_float(a1[2]);
            dacc[1][1] += __uint_as_float(a1[1]) + __uint_as_float(a1[3]);
            #pragma unroll
            for (int p = 0; p < 4; p++) {
                unsigned bx0, bx1, bx2, bx3;
                ldsm_x4(bx0, bx1, bx2, bx3, xBase + (unsigned)(p * 16 * XSTR) * 4u + kbB);
                mma_tf32(c0[2*p][0], c0[2*p][1], c0[2*p][2], c0[2*p][3],
                         a0[0], a0[1], a0[2], a0[3], bx0, bx1);
                mma_tf32(c0[2*p+1][0], c0[2*p+1][1], c0[2*p+1][2], c0[2*p+1][3],
                         a0[0], a0[1], a0[2], a0[3], bx2, bx3);
                mma_tf32(c1[2*p][0], c1[2*p][1], c1[2*p][2], c1[2*p][3],
                         a1[0], a1[1], a1[2], a1[3], bx0, bx1);
                mma_tf32(c1[2*p+1][0], c1[2*p+1][1], c1[2*p+1][2], c1[2*p+1][3],
                         a1[0], a1[1], a1[2], a1[3], bx2, bx3);
            }
        }
        __syncthreads();
    }

    // ---- deg: reduce over the 4 kc lanes, one atomic per row ----
    #pragma unroll
    for (int mt = 0; mt < 2; mt++) {
        float v0 = dacc[mt][0], v1 = dacc[mt][1];
        v0 += __shfl_xor_sync(0xffffffffu, v0, 1);
        v0 += __shfl_xor_sync(0xffffffffu, v0, 2);
        v1 += __shfl_xor_sync(0xffffffffu, v1, 1);
        v1 += __shfl_xor_sync(0xffffffffu, v1, 2);
        int r = (mt == 0) ? r00 : r10;
        if (kc == 0) {
            if (r < n)     atomicAdd(&deg[r], v0);
            if (r + 8 < n) atomicAdd(&deg[r + 8], v1);
        }
    }

    // ---- accumulate split-K partials ----
    const int ccBase = kc * 2;
    #pragma unroll
    for (int mt = 0; mt < 2; mt++) {
        const int r = (mt == 0) ? r00 : r10;
        float (*cc)[4] = (mt == 0) ? c0 : c1;
        #pragma unroll
        for (int nt = 0; nt < 8; nt++) {
            int col = nt * 8 + ccBase;
            if (r < n) {
                atomicAdd(&R[r * D + col],     cc[nt][0]);
                atomicAdd(&R[r * D + col + 1], cc[nt][1]);
            }
            if (r + 8 < n) {
                atomicAdd(&R[(r + 8) * D + col],     cc[nt][2]);
                atomicAdd(&R[(r + 8) * D + col + 1], cc[nt][3]);
            }
        }
    }
}

// ---------------- post: paper-row epilogue + uf/q gather, one launch --------
// Blocks [0, EPB): epilogue on Rup rows [U_N,NUP) and Rgp rows [G_N,NGP)
// Blocks [EPB, EPB+UFB): uf = f(accumulators, deg); q = uf @ W.
#define EP_I4 (2 * P_N * (D / 4))          // 128000 float4 elements
#define EPB ((EP_I4 + 255) / 256)          // 500
#define UFB (B_N / 4)                      // 128

__global__ void __launch_bounds__(256)
post_all(const float4* __restrict__ pe4,
         const float* __restrict__ ue,
         const int* __restrict__ uids,
         const float* __restrict__ W,
         float* __restrict__ out_uf)
{
    int b = blockIdx.x;
    if (b < EPB) {
        int i4 = b * 256 + threadIdx.x;
        if (i4 >= EP_I4) return;
        float4 x, *Rp;
        float d;
        if (i4 < P_N * (D / 4)) {
            int pr = i4 >> 4;
            d = fmaxf(g_deg[U_N + pr], 1e-8f);
            x = pe4[i4];
            Rp = reinterpret_cast<float4*>(g_Rup) + (U_N * (D / 4) + i4);
        } else {
            int j = i4 - P_N * (D / 4);
            int pr = j >> 4;
            d = fmaxf(g_deg[NUP + NGU + G_N + pr], 1e-8f);
            x = pe4[j];
            Rp = reinterpret_cast<float4*>(g_Rgp) + (G_N * (D / 4) + j);
        }
        float4 r = *Rp;
        r.x = (x.x + r.x / d) * 0.5f;
        r.y = (x.y + r.y / d) * 0.5f;
        r.z = (x.z + r.z / d) * 0.5f;
        r.w = (x.w + r.w / d) * 0.5f;
        *Rp = r;
        return;
    }
    // ---- uf/q path (from accumulators; independent of epilogue) ----
    __shared__ float sh[4][D];
    int u  = threadIdx.x >> 6;
    int d  = threadIdx.x & 63;
    int bb = (b - EPB) * 4 + u;
    int uid = uids[bb];
    float dUp = fmaxf(g_deg[uid], 1e-8f);
    float dGu = fmaxf(g_deg[NUP + G_N + uid], 1e-8f);
    float x   = ue[(size_t)uid * D + d];
    float aUp = g_Rup[(size_t)uid * D + d];
    float aGu = g_Rgu[(size_t)(G_N + uid) * D + d];
    float v = 0.5f * ((x + aUp / dUp) * 0.5f + (x + aGu / dGu) * 0.5f);
    sh[u][d] = v;
    g_uf[bb * D + d] = v;
    out_uf[bb * D + d] = v;
    __syncthreads();
    float acc = 0.f;
    #pragma unroll
    for (int k = 0; k < D; k++) acc += sh[u][k] * W[k * D + d];
    g_q[bb * D + d] = acc;
}

// ---------------- score kernel: diff form, RN splits, 6 MMAs ----------------
// z  = q·(i0-i1)                      (plain tf32 hi; feeds sigmoid only)
// dd = uh·(bd_h + bd_l)               (2-term, RN splits: err ~2^-12 rel)
// d1 = uh·(b1_h + b1_l) + ul·b1_h     (3-term: err ~2^-22)
// out = d1 + sigmoid(z/8)·dd
#define SST 72
#define S_SMEM_BYTES (4 * 64 * SST * 4)

extern "C" __global__ void __launch_bounds__(256, 2)
score_all(float* __restrict__ scores)
{
    extern __shared__ float smem[];
    float* Qs  = smem;
    float* Us  = Qs  + 64 * SST;
    float* I1s = Us  + 64 * SST;
    float* IDs = I1s + 64 * SST;

    const int tid   = threadIdx.x;
    const int lane  = tid & 31;
    const int warp  = tid >> 5;
    const int warpB = warp >> 1;
    const int warpP = warp & 1;
    const int rq    = lane >> 2;
    const int kc    = lane & 3;
    const int ub    = blockIdx.y * 64;
    const int pb    = blockIdx.x * 64;

    #pragma unroll
    for (int it = 0; it < 4; it++) {
        int slot = tid + it * 256;
        int r  = slot >> 4;
        int c4 = (slot & 15) << 2;
        float4 q = *reinterpret_cast<const float4*>(&g_q [(size_t)(ub + r) * D + c4]);
        float4 u = *reinterpret_cast<const float4*>(&g_uf[(size_t)(ub + r) * D + c4]);
        *reinterpret_cast<float4*>(&Qs[r * SST + c4]) = q;
        *reinterpret_cast<float4*>(&Us[r * SST + c4]) = u;
        int gp = pb + r;
        float4 v0 = make_float4(0.f, 0.f, 0.f, 0.f), v1 = v0;
        if (gp < P_N) {
            v0 = *reinterpret_cast<const float4*>(&g_Rup[(size_t)(U_N + gp) * D + c4]);
            v1 = *reinterpret_cast<const float4*>(&g_Rgp[(size_t)(G_N + gp) * D + c4]);
        }
        *reinterpret_cast<float4*>(&I1s[r * SST + c4]) = v1;
        float4 dv = make_float4(v0.x - v1.x, v0.y - v1.y, v0.z - v1.z, v0.w - v1.w);
        *reinterpret_cast<float4*>(&IDs[r * SST + c4]) = dv;
    }
    __syncthreads();

    float z[4][4] = {}, dd[4][4] = {}, d1[4][4] = {};
    const int ar = warpB * 16 + rq;

    #pragma unroll
    for (int ks = 0; ks < 8; ks++) {
        int kb = ks * 8;
        unsigned aq[4];
        float uf[4];
        aq[0] = __float_as_uint(Qs[ar * SST + kb + kc]);
        aq[1] = __float_as_uint(Qs[(ar + 8) * SST + kb + kc]);
        aq[2] = __float_as_uint(Qs[ar * SST + kb + kc + 4]);
        aq[3] = __float_as_uint(Qs[(ar + 8) * SST + kb + kc + 4]);
        uf[0] = Us[ar * SST + kb + kc];
        uf[1] = Us[(ar + 8) * SST + kb + kc];
        uf[2] = Us[ar * SST + kb + kc + 4];
        uf[3] = Us[(ar + 8) * SST + kb + kc + 4];
        unsigned uh[4], ul[4];
        #pragma unroll
        for (int j = 0; j < 4; j++) split_rn(uf[j], uh[j], ul[j]);

        #pragma unroll
        for (int nt = 0; nt < 4; nt++) {
            int col = warpP * 32 + nt * 8 + rq;
            float bd0 = IDs[col * SST + kb + kc];
            float bd1 = IDs[col * SST + kb + kc + 4];
            float b10 = I1s[col * SST + kb + kc];
            float b11 = I1s[col * SST + kb + kc + 4];
            unsigned hd0, ld0, hd1, ld1, h10, l10, h11, l11;
            split_rn(bd0, hd0, ld0); split_rn(bd1, hd1, ld1);
            split_rn(b10, h10, l10); split_rn(b11, h11, l11);

            // z: plain tf32 on diff (sigmoid input)
            mma_tf32(z[nt][0], z[nt][1], z[nt][2], z[nt][3],
                     aq[0], aq[1], aq[2], aq[3], hd0, hd1);
            // dd: 2-term (RN)
            mma_tf32(dd[nt][0], dd[nt][1], dd[nt][2], dd[nt][3],
                     uh[0], uh[1], uh[2], uh[3], hd0, hd1);
            mma_tf32(dd[nt][0], dd[nt][1], dd[nt][2], dd[nt][3],
                     uh[0], uh[1], uh[2], uh[3], ld0, ld1);
            // d1: 3-term
            mma_tf32(d1[nt][0], d1[nt][1], d1[nt][2], d1[nt][3],
                     uh[0], uh[1], uh[2], uh[3], h10, h11);
            mma_tf32(d1[nt][0], d1[nt][1], d1[nt][2], d1[nt][3],
                     uh[0], uh[1], uh[2], uh[3], l10, l11);
            mma_tf32(d1[nt][0], d1[nt][1], d1[nt][2], d1[nt][3],
                     ul[0], ul[1], ul[2], ul[3], h10, h11);
        }
    }

    const float scale = 0.125f;
    #pragma unroll
    for (int nt = 0; nt < 4; nt++) {
        #pragma unroll
        for (int j = 0; j < 4; j++) {
            int r = ub + warpB * 16 + rq + ((j >= 2) ? 8 : 0);
            int p = pb + warpP * 32 + nt * 8 + kc * 2 + (j & 1);
            if (p < P_N) {
                float a0 = 1.f / (1.f + expf(-z[nt][j] * scale));
                scores[(size_t)r * P_N + p] = d1[nt][j] + a0 * dd[nt][j];
            }
        }
    }
}

// ---------------- launch -----------------------------------------------------
extern "C" void kernel_launch(void* const* d_in, const int* in_sizes, int n_in,
                              void* d_out, int out_size)
{
    const float* A_up = (const float*)d_in[0];
    const float* A_gu = (const float*)d_in[1];
    const float* A_gp = (const float*)d_in[2];
    const float* ue   = (const float*)d_in[3];
    const float* pe   = (const float*)d_in[4];
    const float* ge   = (const float*)d_in[5];
    const float* W    = (const float*)d_in[6];
    const int*   uids = (const int*)d_in[7];
    float* out = (float*)d_out;

    float *pXT0, *pXT1, *pXT2, *pRup, *pRgu, *pRgp, *pdeg;
    cudaGetSymbolAddress((void**)&pXT0, g_XT0);
    cudaGetSymbolAddress((void**)&pXT1, g_XT1);
    cudaGetSymbolAddress((void**)&pXT2, g_XT2);
    cudaGetSymbolAddress((void**)&pRup, g_Rup);
    cudaGetSymbolAddress((void**)&pRgu, g_Rgu);
    cudaGetSymbolAddress((void**)&pRgp, g_Rgp);
    cudaGetSymbolAddress((void**)&pdeg, g_deg);

    cudaFuncSetAttribute(gemm_all,  cudaFuncAttributeMaxDynamicSharedMemorySize, G_SMEM_BYTES);
    cudaFuncSetAttribute(score_all, cudaFuncAttributeMaxDynamicSharedMemorySize, S_SMEM_BYTES);

    init_and_transpose<<<TPALL + ZBLK, 256>>>(ue, pe, ge);

    gemm_all<<<NBLK, 128, G_SMEM_BYTES>>>(A_up, A_gu, A_gp,
                                          pXT0, pXT1, pXT2,
                                          pRup, pRgu, pRgp, pdeg);

    post_all<<<EPB + UFB, 256>>>((const float4*)pe, ue, uids, W,
                                 out + (size_t)B_N * P_N);

    dim3 sg((P_N + 63) / 64, B_N / 64);
    score_all<<<sg, 256, S_SMEM_BYTES>>>(out);
}

// round 15
// speedup vs baseline: 1.1315x; 1.0253x over previous
#include <cuda_runtime.h>
#include <cuda_fp16.h>
#include <math.h>
#include <stdint.h>

#define U_N 4000
#define P_N 4000
#define G_N 200
#define D   64
#define B_N 512
#define NUP (U_N + P_N)   // 8000
#define NGU (G_N + U_N)   // 4200
#define NGP (G_N + P_N)   // 4200
#define NTOT (NUP + NGU + NGP)

// ---------------- scratch (device globals; no allocation allowed) ----------
__device__ __align__(16) float g_XT0[D * NUP];   // transposed X (N-major rows)
__device__ __align__(16) float g_XT1[D * NGU];
__device__ __align__(16) float g_XT2[D * NGP];
__device__ __align__(16) float g_Rup[NUP * D];   // accumulators -> propagated
__device__ __align__(16) float g_Rgu[NGU * D];
__device__ __align__(16) float g_Rgp[NGP * D];
__device__ float g_deg[NTOT];
__device__ __align__(16) float g_uf[B_N * D];
__device__ __align__(16) float g_q [B_N * D];

// ---------------- merged init: transpose-build X^T + zero R/deg -------------
#define TP0 (250 * 2)
#define TP12 (132 * 2)
#define TPALL (TP0 + 2 * TP12)              // 764 transpose blocks
#define ZBLK ((NUP * (D / 4) + 255) / 256)  // 500 zero blocks
__global__ void init_and_transpose(const float* __restrict__ ue,
                                   const float* __restrict__ pe,
                                   const float* __restrict__ ge)
{
    int b = blockIdx.x;
    if (b >= TPALL) {
        int i4 = (b - TPALL) * blockDim.x + threadIdx.x;
        const float4 z = make_float4(0.f, 0.f, 0.f, 0.f);
        if (i4 < NUP * (D / 4)) ((float4*)g_Rup)[i4] = z;
        if (i4 < NGU * (D / 4)) {
            ((float4*)g_Rgu)[i4] = z;
            ((float4*)g_Rgp)[i4] = z;
        }
        if (i4 < NTOT) g_deg[i4] = 0.f;
        return;
    }
    __shared__ float t[32][33];
    int prob, tile, n;
    float* dst;
    if (b < TP0)            { prob = 0; tile = b;               n = NUP; dst = g_XT0; }
    else if (b < TP0 + TP12){ prob = 1; tile = b - TP0;         n = NGU; dst = g_XT1; }
    else                    { prob = 2; tile = b - TP0 - TP12;  n = NGP; dst = g_XT2; }

    const int rt = tile >> 1;
    const int ct = tile & 1;
    const int r0 = rt * 32;
    const int d0 = ct * 32;
    const int tx = threadIdx.x & 31;
    const int ty = threadIdx.x >> 5;

    #pragma unroll
    for (int j = 0; j < 4; j++) {
        int rr = ty + j * 8;
        int r  = r0 + rr;
        int d  = d0 + tx;
        float v = 0.f;
        if (r < n) {
            if (prob == 0) v = (r < U_N) ? ue[(size_t)r * D + d] : pe[(size_t)(r - U_N) * D + d];
            else if (prob == 1) v = (r < G_N) ? ge[(size_t)r * D + d] : ue[(size_t)(r - G_N) * D + d];
            else v = (r < G_N) ? ge[(size_t)r * D + d] : pe[(size_t)(r - G_N) * D + d];
        }
        t[rr][tx] = v;
    }
    __syncthreads();
    const int r = r0 + tx;
    if (r < n) {
        #pragma unroll
        for (int j = 0; j < 4; j++) {
            int dd = ty + j * 8;
            dst[(size_t)(d0 + dd) * n + r] = t[tx][dd];
        }
    }
}

// ---------------- helpers ----------------------------------------------------
__device__ __forceinline__ unsigned smem_u32(const void* p)
{
    return (unsigned)__cvta_generic_to_shared(p);
}
__device__ __forceinline__ void mbar_init(unsigned mb, int count)
{
    asm volatile("mbarrier.init.shared.b64 [%0], %1;" :: "r"(mb), "r"(count) : "memory");
}
__device__ __forceinline__ void mbar_expect_tx(unsigned mb, unsigned bytes)
{
    asm volatile("mbarrier.arrive.expect_tx.shared.b64 _, [%0], %1;"
                 :: "r"(mb), "r"(bytes) : "memory");
}
__device__ __forceinline__ void mbar_wait(unsigned mb, int phase)
{
    asm volatile(
        "{\n\t"
        ".reg .pred P;\n\t"
        "W_%=:\n\t"
        "mbarrier.try_wait.parity.acquire.cta.shared::cta.b64 P, [%0], %1, 0x989680;\n\t"
        "@P bra D_%=;\n\t"
        "bra W_%=;\n\t"
        "D_%=:\n\t"
        "}"
        :: "r"(mb), "r"(phase) : "memory");
}
__device__ __forceinline__ void bulk_cp(unsigned smem_dst, const void* gmem_src,
                                        unsigned bytes, unsigned mb)
{
    asm volatile(
        "cp.async.bulk.shared::cluster.global.mbarrier::complete_tx::bytes [%0], [%1], %2, [%3];"
        :: "r"(smem_dst), "l"(gmem_src), "r"(bytes), "r"(mb) : "memory");
}
__device__ __forceinline__ void ldsm_x4(unsigned& r0, unsigned& r1,
                                        unsigned& r2, unsigned& r3, unsigned addr)
{
    asm volatile("ldmatrix.sync.aligned.m8n8.x4.shared.b16 {%0,%1,%2,%3}, [%4];"
                 : "=r"(r0), "=r"(r1), "=r"(r2), "=r"(r3) : "r"(addr));
}
__device__ __forceinline__ void mma_tf32(
    float& c0, float& c1, float& c2, float& c3,
    unsigned a0, unsigned a1, unsigned a2, unsigned a3,
    unsigned b0, unsigned b1)
{
    asm volatile(
        "mma.sync.aligned.m16n8k8.row.col.f32.tf32.tf32.f32 "
        "{%0,%1,%2,%3}, {%4,%5,%6,%7}, {%8,%9}, {%0,%1,%2,%3};\n"
        : "+f"(c0), "+f"(c1), "+f"(c2), "+f"(c3)
        : "r"(a0), "r"(a1), "r"(a2), "r"(a3), "r"(b0), "r"(b1));
}
__device__ __forceinline__ void mma_f16(
    float& c0, float& c1, float& c2, float& c3,
    unsigned a0, unsigned a1, unsigned a2, unsigned a3,
    unsigned b0, unsigned b1)
{
    asm volatile(
        "mma.sync.aligned.m16n8k16.row.col.f32.f16.f16.f32 "
        "{%0,%1,%2,%3}, {%4,%5,%6,%7}, {%8,%9}, {%0,%1,%2,%3};\n"
        : "+f"(c0), "+f"(c1), "+f"(c2), "+f"(c3)
        : "r"(a0), "r"(a1), "r"(a2), "r"(a3), "r"(b0), "r"(b1));
}

// ---------------- propagation GEMM (R9 config — best measured) --------------
#define BM 128
#define BKK 64
#define ASTR 68
#define XSTR 68
#define A_SZ (BM * ASTR)
#define X_SZ (D * XSTR)
#define STG (A_SZ + X_SZ)
#define G_SMEM_BYTES (2 * STG * 4)

#define RT0 63
#define RT12 33
#define KS0 16
#define KS12 8
#define KPS0 8
#define KPS12 9
#define NB0 (RT0 * KS0)        // 1008
#define NB12 (RT12 * KS12)     // 264
#define NBLK (NB0 + 2 * NB12)  // 1536

__device__ __forceinline__ void issue_stage(
    float* Abuf, float* Xbuf, unsigned mb,
    const float* __restrict__ A, const float* __restrict__ XT,
    int n, int rowBase, int k0, int kEnd, int tid)
{
    const int kChunk = min(BKK, kEnd - k0);
    const unsigned kBytes = (unsigned)kChunk * 4u;
    if (tid == 0) {
        int nA = min(BM, n - rowBase);
        mbar_expect_tx(mb, (unsigned)nA * kBytes + (unsigned)D * kBytes);
    }
    {
        int gr = rowBase + tid;
        if (gr < n)
            bulk_cp(smem_u32(Abuf + tid * ASTR), A + (size_t)gr * n + k0, kBytes, mb);
    }
    if (tid < D)
        bulk_cp(smem_u32(Xbuf + tid * XSTR), XT + (size_t)tid * n + k0, kBytes, mb);
}

extern "C" __global__ void __launch_bounds__(128, 2)
gemm_all(const float* __restrict__ A0, const float* __restrict__ A1,
         const float* __restrict__ A2,
         const float* __restrict__ XT0, const float* __restrict__ XT1,
         const float* __restrict__ XT2,
         float* __restrict__ R0, float* __restrict__ R1, float* __restrict__ R2,
         float* __restrict__ degAll)
{
    extern __shared__ float dyn[];
    __shared__ uint64_t mbar[2];

    float* AbufS[2] = { dyn,        dyn + STG };
    float* XbufS[2] = { dyn + A_SZ, dyn + STG + A_SZ };

    const int tid  = threadIdx.x;
    const int lane = tid & 31;
    const int warp = tid >> 5;
    const int rq   = lane >> 2;
    const int kc   = lane & 3;
    const int wrow = warp * 32;

    const unsigned aLaneOff =
        (unsigned)(((lane & 7) + ((lane >> 3) & 1) * 8 + wrow) * ASTR) * 4u
        + (unsigned)(lane >> 4) * 16u;
    const unsigned xLaneOff =
        (unsigned)(((lane & 7) + (lane >> 4) * 8) * XSTR) * 4u
        + (unsigned)((lane >> 3) & 1) * 16u;

    // ---- map block -> (problem, rowTile, ksplit) ----
    const float *A, *XT; float *R, *deg;
    int n, kIters, kps, rowTile, split;
    int b = blockIdx.x;
    if (b < NB0) {
        A = A0; XT = XT0; R = R0; deg = degAll; n = NUP; kIters = 125; kps = KPS0;
        rowTile = b % RT0; split = b / RT0;
    } else {
        int idx = b - NB0;
        if (idx < NB12) { A = A1; XT = XT1; R = R1; deg = degAll + NUP;       n = NGU; }
        else            { A = A2; XT = XT2; R = R2; deg = degAll + NUP + NGU; n = NGP; idx -= NB12; }
        kIters = 66; kps = KPS12;
        rowTile = idx % RT12; split = idx / RT12;
    }

    const int rowBase = rowTile * BM;
    const int itStart = split * kps;
    const int itEnd   = min(kIters, itStart + kps);
    const int nIt     = itEnd - itStart;
    if (nIt <= 0) return;
    const int kEnd = min(n, itEnd * BKK);

    if (tid == 0) { mbar_init(smem_u32(&mbar[0]), 1); mbar_init(smem_u32(&mbar[1]), 1); }
    __syncthreads();

    issue_stage(AbufS[0], XbufS[0], smem_u32(&mbar[0]), A, XT, n, rowBase,
                itStart * BKK, kEnd, tid);

    float c0[8][4], c1[8][4];
    #pragma unroll
    for (int nt = 0; nt < 8; nt++)
        #pragma unroll
        for (int j = 0; j < 4; j++) { c0[nt][j] = 0.f; c1[nt][j] = 0.f; }
    float dacc[2][2] = {{0.f, 0.f}, {0.f, 0.f}};

    const int r00 = rowBase + wrow + rq;
    const int r10 = r00 + 16;
    int ph0 = 0, ph1 = 0;

    for (int i = 0; i < nIt; i++) {
        const int cur = i & 1;
        const int k0  = (itStart + i) * BKK;

        if (i + 1 < nIt)
            issue_stage(AbufS[cur ^ 1], XbufS[cur ^ 1], smem_u32(&mbar[cur ^ 1]),
                        A, XT, n, rowBase, k0 + BKK, kEnd, tid);

        if (cur == 0) { mbar_wait(smem_u32(&mbar[0]), ph0); ph0 ^= 1; }
        else          { mbar_wait(smem_u32(&mbar[1]), ph1); ph1 ^= 1; }

        const unsigned aBase = smem_u32(AbufS[cur]) + aLaneOff;
        const unsigned xBase = smem_u32(XbufS[cur]) + xLaneOff;
        const int kSteps = min(BKK, kEnd - k0) >> 3;

        #pragma unroll 8
        for (int ks = 0; ks < kSteps; ks++) {
            const unsigned kbB = (unsigned)(ks * 8) * 4u;
            unsigned a0[4], a1[4];
            ldsm_x4(a0[0], a0[1], a0[2], a0[3], aBase + kbB);
            ldsm_x4(a1[0], a1[1], a1[2], a1[3], aBase + 16u * ASTR * 4u + kbB);
            dacc[0][0] += __uint_as_float(a0[0]) + __uint_as_float(a0[2]);
            dacc[0][1] += __uint_as_float(a0[1]) + __uint_as_float(a0[3]);
            dacc[1][0] += __uint_as_float(a1[0]) + __uint_as_float(a1[2]);
            dacc[1][1] += __uint_as_float(a1[1]) + __uint_as_float(a1[3]);
            #pragma unroll
            for (int p = 0; p < 4; p++) {
                unsigned bx0, bx1, bx2, bx3;
                ldsm_x4(bx0, bx1, bx2, bx3, xBase + (unsigned)(p * 16 * XSTR) * 4u + kbB);
                mma_tf32(c0[2*p][0], c0[2*p][1], c0[2*p][2], c0[2*p][3],
                         a0[0], a0[1], a0[2], a0[3], bx0, bx1);
                mma_tf32(c0[2*p+1][0], c0[2*p+1][1], c0[2*p+1][2], c0[2*p+1][3],
                         a0[0], a0[1], a0[2], a0[3], bx2, bx3);
                mma_tf32(c1[2*p][0], c1[2*p][1], c1[2*p][2], c1[2*p][3],
                         a1[0], a1[1], a1[2], a1[3], bx0, bx1);
                mma_tf32(c1[2*p+1][0], c1[2*p+1][1], c1[2*p+1][2], c1[2*p+1][3],
                         a1[0], a1[1], a1[2], a1[3], bx2, bx3);
            }
        }
        __syncthreads();
    }

    // ---- deg: reduce over the 4 kc lanes, one atomic per row ----
    #pragma unroll
    for (int mt = 0; mt < 2; mt++) {
        float v0 = dacc[mt][0], v1 = dacc[mt][1];
        v0 += __shfl_xor_sync(0xffffffffu, v0, 1);
        v0 += __shfl_xor_sync(0xffffffffu, v0, 2);
        v1 += __shfl_xor_sync(0xffffffffu, v1, 1);
        v1 += __shfl_xor_sync(0xffffffffu, v1, 2);
        int r = (mt == 0) ? r00 : r10;
        if (kc == 0) {
            if (r < n)     atomicAdd(&deg[r], v0);
            if (r + 8 < n) atomicAdd(&deg[r + 8], v1);
        }
    }

    // ---- accumulate split-K partials ----
    const int ccBase = kc * 2;
    #pragma unroll
    for (int mt = 0; mt < 2; mt++) {
        const int r = (mt == 0) ? r00 : r10;
        float (*cc)[4] = (mt == 0) ? c0 : c1;
        #pragma unroll
        for (int nt = 0; nt < 8; nt++) {
            int col = nt * 8 + ccBase;
            if (r < n) {
                atomicAdd(&R[r * D + col],     cc[nt][0]);
                atomicAdd(&R[r * D + col + 1], cc[nt][1]);
            }
            if (r + 8 < n) {
                atomicAdd(&R[(r + 8) * D + col],     cc[nt][2]);
                atomicAdd(&R[(r + 8) * D + col + 1], cc[nt][3]);
            }
        }
    }
}

// ---------------- post: paper-row epilogue + uf/q gather, one launch --------
#define EP_I4 (2 * P_N * (D / 4))          // 128000 float4 elements
#define EPB ((EP_I4 + 255) / 256)          // 500
#define UFB (B_N / 4)                      // 128

__global__ void __launch_bounds__(256)
post_all(const float4* __restrict__ pe4,
         const float* __restrict__ ue,
         const int* __restrict__ uids,
         const float* __restrict__ W,
         float* __restrict__ out_uf)
{
    int b = blockIdx.x;
    if (b < EPB) {
        int i4 = b * 256 + threadIdx.x;
        if (i4 >= EP_I4) return;
        float4 x, *Rp;
        float d;
        if (i4 < P_N * (D / 4)) {
            int pr = i4 >> 4;
            d = fmaxf(g_deg[U_N + pr], 1e-8f);
            x = pe4[i4];
            Rp = reinterpret_cast<float4*>(g_Rup) + (U_N * (D / 4) + i4);
        } else {
            int j = i4 - P_N * (D / 4);
            int pr = j >> 4;
            d = fmaxf(g_deg[NUP + NGU + G_N + pr], 1e-8f);
            x = pe4[j];
            Rp = reinterpret_cast<float4*>(g_Rgp) + (G_N * (D / 4) + j);
        }
        float4 r = *Rp;
        r.x = (x.x + r.x / d) * 0.5f;
        r.y = (x.y + r.y / d) * 0.5f;
        r.z = (x.z + r.z / d) * 0.5f;
        r.w = (x.w + r.w / d) * 0.5f;
        *Rp = r;
        return;
    }
    __shared__ float sh[4][D];
    int u  = threadIdx.x >> 6;
    int d  = threadIdx.x & 63;
    int bb = (b - EPB) * 4 + u;
    int uid = uids[bb];
    float dUp = fmaxf(g_deg[uid], 1e-8f);
    float dGu = fmaxf(g_deg[NUP + G_N + uid], 1e-8f);
    float x   = ue[(size_t)uid * D + d];
    float aUp = g_Rup[(size_t)uid * D + d];
    float aGu = g_Rgu[(size_t)(G_N + uid) * D + d];
    float v = 0.5f * ((x + aUp / dUp) * 0.5f + (x + aGu / dGu) * 0.5f);
    sh[u][d] = v;
    g_uf[bb * D + d] = v;
    out_uf[bb * D + d] = v;
    __syncthreads();
    float acc = 0.f;
    #pragma unroll
    for (int k = 0; k < D; k++) acc += sh[u][k] * W[k * D + d];
    g_q[bb * D + d] = acc;
}

// ---------------- score kernel: fp16-pair MMA (m16n8k16), RN splits ---------
// Precompute per-block fp16 splits in smem (once), then pure ldmatrix+HMMA.
// z  = qh·idh              (hi only; feeds sigmoid)
// dd = uh·idh + uh·idl     (2-term RN)
// d1 = uh·i1h + uh·i1l + ul·i1h  (3-term)
// out = d1 + sigmoid(z/8)·dd
#define SSTH 72                                   // halfs per smem row (144 B)
#define HARR (64 * SSTH)                          // halfs per array
#define S_SMEM_BYTES (7 * HARR * 2)               // 64512 B

__device__ __forceinline__ void split_h(float x, __half& h, __half& l)
{
    h = __float2half_rn(x);
    l = __float2half_rn(x - __half2float(h));
}

extern "C" __global__ void __launch_bounds__(256, 2)
score_all(float* __restrict__ scores)
{
    extern __shared__ __half hsm[];
    __half* Qh  = hsm;
    __half* Uh  = hsm + 1 * HARR;
    __half* Ul  = hsm + 2 * HARR;
    __half* IDh = hsm + 3 * HARR;
    __half* IDl = hsm + 4 * HARR;
    __half* I1h = hsm + 5 * HARR;
    __half* I1l = hsm + 6 * HARR;

    const int tid   = threadIdx.x;
    const int lane  = tid & 31;
    const int warp  = tid >> 5;
    const int warpB = warp >> 1;     // 4 groups of 16 users
    const int warpP = warp & 1;      // 2 groups of 32 papers
    const int rq    = lane >> 2;
    const int kc    = lane & 3;
    const int ub    = blockIdx.y * 64;
    const int pb    = blockIdx.x * 64;

    // ---- prologue: load fp32, split to fp16 hi/lo once per block ----
    #pragma unroll
    for (int it = 0; it < 4; it++) {
        int slot = tid + it * 256;
        int r  = slot >> 4;
        int c4 = (slot & 15) << 2;
        float4 q = *reinterpret_cast<const float4*>(&g_q [(size_t)(ub + r) * D + c4]);
        float4 u = *reinterpret_cast<const float4*>(&g_uf[(size_t)(ub + r) * D + c4]);
        int gp = pb + r;
        float4 v0 = make_float4(0.f, 0.f, 0.f, 0.f), v1 = v0;
        if (gp < P_N) {
            v0 = *reinterpret_cast<const float4*>(&g_Rup[(size_t)(U_N + gp) * D + c4]);
            v1 = *reinterpret_cast<const float4*>(&g_Rgp[(size_t)(G_N + gp) * D + c4]);
        }
        float dv[4] = { v0.x - v1.x, v0.y - v1.y, v0.z - v1.z, v0.w - v1.w };
        float qa[4] = { q.x, q.y, q.z, q.w };
        float ua[4] = { u.x, u.y, u.z, u.w };
        float oa[4] = { v1.x, v1.y, v1.z, v1.w };
        const int base = r * SSTH + c4;
        #pragma unroll
        for (int j = 0; j < 4; j++) {
            Qh[base + j] = __float2half_rn(qa[j]);
            __half h, l;
            split_h(ua[j], h, l); Uh[base + j] = h; Ul[base + j] = l;
            split_h(dv[j], h, l); IDh[base + j] = h; IDl[base + j] = l;
            split_h(oa[j], h, l); I1h[base + j] = h; I1l[base + j] = l;
        }
    }
    __syncthreads();

    float z[4][4] = {}, dd[4][4] = {}, d1[4][4] = {};

    // ldmatrix lane offsets (bytes). A (users): rows warpB*16 + tile pattern.
    const unsigned aOff =
        (unsigned)(((lane & 7) + ((lane >> 3) & 1) * 8 + warpB * 16) * SSTH) * 2u
        + (unsigned)(lane >> 4) * 16u;
    // B (papers): pair p covers papers 16p..16p+15 within warpP half.
    const unsigned bOffBase =
        (unsigned)(((lane & 7) + ((lane >> 3) & 1) * 8 + warpP * 32) * SSTH) * 2u
        + (unsigned)(lane >> 4) * 16u;

    const unsigned qhB  = smem_u32(Qh)  + aOff;
    const unsigned uhB  = smem_u32(Uh)  + aOff;
    const unsigned ulB  = smem_u32(Ul)  + aOff;
    const unsigned idhB = smem_u32(IDh) + bOffBase;
    const unsigned idlB = smem_u32(IDl) + bOffBase;
    const unsigned i1hB = smem_u32(I1h) + bOffBase;
    const unsigned i1lB = smem_u32(I1l) + bOffBase;

    #pragma unroll
    for (int ks = 0; ks < 4; ks++) {          // k16 steps over D=64
        const unsigned kb = (unsigned)(ks * 32);   // 16 halfs = 32 B
        unsigned qh[4], uh[4], ul[4];
        ldsm_x4(qh[0], qh[1], qh[2], qh[3], qhB + kb);
        ldsm_x4(uh[0], uh[1], uh[2], uh[3], uhB + kb);
        ldsm_x4(ul[0], ul[1], ul[2], ul[3], ulB + kb);

        #pragma unroll
        for (int p = 0; p < 2; p++) {          // paper pairs: nt = 2p, 2p+1
            const unsigned po = (unsigned)(p * 16 * SSTH) * 2u + kb;
            unsigned dh0, dh1, dh2, dh3, dl0, dl1, dl2, dl3;
            unsigned oh0, oh1, oh2, oh3, ol0, ol1, ol2, ol3;
            ldsm_x4(dh0, dh1, dh2, dh3, idhB + po);
            ldsm_x4(dl0, dl1, dl2, dl3, idlB + po);
            ldsm_x4(oh0, oh1, oh2, oh3, i1hB + po);
            ldsm_x4(ol0, ol1, ol2, ol3, i1lB + po);

            // nt = 2p : B-frags {x0, x2}
            mma_f16(z[2*p][0], z[2*p][1], z[2*p][2], z[2*p][3],
                    qh[0], qh[1], qh[2], qh[3], dh0, dh2);
            mma_f16(dd[2*p][0], dd[2*p][1], dd[2*p][2], dd[2*p][3],
                    uh[0], uh[1], uh[2], uh[3], dh0, dh2);
            mma_f16(dd[2*p][0], dd[2*p][1], dd[2*p][2], dd[2*p][3],
                    uh[0], uh[1], uh[2], uh[3], dl0, dl2);
            mma_f16(d1[2*p][0], d1[2*p][1], d1[2*p][2], d1[2*p][3],
                    uh[0], uh[1], uh[2], uh[3], oh0, oh2);
            mma_f16(d1[2*p][0], d1[2*p][1], d1[2*p][2], d1[2*p][3],
                    uh[0], uh[1], uh[2], uh[3], ol0, ol2);
            mma_f16(d1[2*p][0], d1[2*p][1], d1[2*p][2], d1[2*p][3],
                    ul[0], ul[1], ul[2], ul[3], oh0, oh2);
            // nt = 2p+1 : B-frags {x1, x3}
            mma_f16(z[2*p+1][0], z[2*p+1][1], z[2*p+1][2], z[2*p+1][3],
                    qh[0], qh[1], qh[2], qh[3], dh1, dh3);
            mma_f16(dd[2*p+1][0], dd[2*p+1][1], dd[2*p+1][2], dd[2*p+1][3],
                    uh[0], uh[1], uh[2], uh[3], dh1, dh3);
            mma_f16(dd[2*p+1][0], dd[2*p+1][1], dd[2*p+1][2], dd[2*p+1][3],
                    uh[0], uh[1], uh[2], uh[3], dl1, dl3);
            mma_f16(d1[2*p+1][0], d1[2*p+1][1], d1[2*p+1][2], d1[2*p+1][3],
                    uh[0], uh[1], uh[2], uh[3], oh1, oh3);
            mma_f16(d1[2*p+1][0], d1[2*p+1][1], d1[2*p+1][2], d1[2*p+1][3],
                    uh[0], uh[1], uh[2], uh[3], ol1, ol3);
            mma_f16(d1[2*p+1][0], d1[2*p+1][1], d1[2*p+1][2], d1[2*p+1][3],
                    ul[0], ul[1], ul[2], ul[3], oh1, oh3);
        }
    }

    const float scale = 0.125f;   // 1/sqrt(64)
    #pragma unroll
    for (int nt = 0; nt < 4; nt++) {
        #pragma unroll
        for (int j = 0; j < 4; j++) {
            int r = ub + warpB * 16 + rq + ((j >= 2) ? 8 : 0);
            int p = pb + warpP * 32 + nt * 8 + kc * 2 + (j & 1);
            if (p < P_N) {
                float a0 = 1.f / (1.f + expf(-z[nt][j] * scale));
                scores[(size_t)r * P_N + p] = d1[nt][j] + a0 * dd[nt][j];
            }
        }
    }
}

// ---------------- launch -----------------------------------------------------
extern "C" void kernel_launch(void* const* d_in, const int* in_sizes, int n_in,
                              void* d_out, int out_size)
{
    const float* A_up = (const float*)d_in[0];
    const float* A_gu = (const float*)d_in[1];
    const float* A_gp = (const float*)d_in[2];
    const float* ue   = (const float*)d_in[3];
    const float* pe   = (const float*)d_in[4];
    const float* ge   = (const float*)d_in[5];
    const float* W    = (const float*)d_in[6];
    const int*   uids = (const int*)d_in[7];
    float* out = (float*)d_out;

    float *pXT0, *pXT1, *pXT2, *pRup, *pRgu, *pRgp, *pdeg;
    cudaGetSymbolAddress((void**)&pXT0, g_XT0);
    cudaGetSymbolAddress((void**)&pXT1, g_XT1);
    cudaGetSymbolAddress((void**)&pXT2, g_XT2);
    cudaGetSymbolAddress((void**)&pRup, g_Rup);
    cudaGetSymbolAddress((void**)&pRgu, g_Rgu);
    cudaGetSymbolAddress((void**)&pRgp, g_Rgp);
    cudaGetSymbolAddress((void**)&pdeg, g_deg);

    cudaFuncSetAttribute(gemm_all,  cudaFuncAttributeMaxDynamicSharedMemorySize, G_SMEM_BYTES);
    cudaFuncSetAttribute(score_all, cudaFuncAttributeMaxDynamicSharedMemorySize, S_SMEM_BYTES);

    init_and_transpose<<<TPALL + ZBLK, 256>>>(ue, pe, ge);

    gemm_all<<<NBLK, 128, G_SMEM_BYTES>>>(A_up, A_gu, A_gp,
                                          pXT0, pXT1, pXT2,
                                          pRup, pRgu, pRgp, pdeg);

    post_all<<<EPB + UFB, 256>>>((const float4*)pe, ue, uids, W,
                                 out + (size_t)B_N * P_N);

    dim3 sg((P_N + 63) / 64, B_N / 64);
    score_all<<<sg, 256, S_SMEM_BYTES>>>(out);
}

// round 17
// speedup vs baseline: 1.1320x; 1.0004x over previous
#include <cuda_runtime.h>
#include <cuda_fp16.h>
#include <math.h>
#include <stdint.h>

#define U_N 4000
#define P_N 4000
#define G_N 200
#define D   64
#define B_N 512
#define NUP (U_N + P_N)   // 8000
#define NGU (G_N + U_N)   // 4200
#define NGP (G_N + P_N)   // 4200
#define NTOT (NUP + NGU + NGP)

// ---------------- scratch (device globals; no allocation allowed) ----------
__device__ __align__(16) float g_XT0[D * NUP];   // transposed X (N-major rows)
__device__ __align__(16) float g_XT1[D * NGU];
__device__ __align__(16) float g_XT2[D * NGP];
__device__ __align__(16) float g_Rup[NUP * D];   // gemm accumulators
__device__ __align__(16) float g_Rgu[NGU * D];
__device__ __align__(16) float g_Rgp[NGP * D];
__device__ float g_deg[NTOT];
// fp16 split operands for the score kernel (built once in post_all)
__device__ __align__(16) __half g_IDh[P_N * D];
__device__ __align__(16) __half g_IDl[P_N * D];
__device__ __align__(16) __half g_I1h[P_N * D];
__device__ __align__(16) __half g_I1l[P_N * D];
__device__ __align__(16) __half g_Qh [B_N * D];
__device__ __align__(16) __half g_Uh [B_N * D];
__device__ __align__(16) __half g_Ul [B_N * D];

// ---------------- merged init: transpose-build X^T + zero R/deg -------------
#define TP0 (250 * 2)
#define TP12 (132 * 2)
#define TPALL (TP0 + 2 * TP12)              // 764 transpose blocks
#define ZBLK ((NUP * (D / 4) + 255) / 256)  // 500 zero blocks
__global__ void init_and_transpose(const float* __restrict__ ue,
                                   const float* __restrict__ pe,
                                   const float* __restrict__ ge)
{
    int b = blockIdx.x;
    if (b >= TPALL) {
        int i4 = (b - TPALL) * blockDim.x + threadIdx.x;
        const float4 z = make_float4(0.f, 0.f, 0.f, 0.f);
        if (i4 < NUP * (D / 4)) ((float4*)g_Rup)[i4] = z;
        if (i4 < NGU * (D / 4)) {
            ((float4*)g_Rgu)[i4] = z;
            ((float4*)g_Rgp)[i4] = z;
        }
        if (i4 < NTOT) g_deg[i4] = 0.f;
        return;
    }
    __shared__ float t[32][33];
    int prob, tile, n;
    float* dst;
    if (b < TP0)            { prob = 0; tile = b;               n = NUP; dst = g_XT0; }
    else if (b < TP0 + TP12){ prob = 1; tile = b - TP0;         n = NGU; dst = g_XT1; }
    else                    { prob = 2; tile = b - TP0 - TP12;  n = NGP; dst = g_XT2; }

    const int rt = tile >> 1;
    const int ct = tile & 1;
    const int r0 = rt * 32;
    const int d0 = ct * 32;
    const int tx = threadIdx.x & 31;
    const int ty = threadIdx.x >> 5;

    #pragma unroll
    for (int j = 0; j < 4; j++) {
        int rr = ty + j * 8;
        int r  = r0 + rr;
        int d  = d0 + tx;
        float v = 0.f;
        if (r < n) {
            if (prob == 0) v = (r < U_N) ? ue[(size_t)r * D + d] : pe[(size_t)(r - U_N) * D + d];
            else if (prob == 1) v = (r < G_N) ? ge[(size_t)r * D + d] : ue[(size_t)(r - G_N) * D + d];
            else v = (r < G_N) ? ge[(size_t)r * D + d] : pe[(size_t)(r - G_N) * D + d];
        }
        t[rr][tx] = v;
    }
    __syncthreads();
    const int r = r0 + tx;
    if (r < n) {
        #pragma unroll
        for (int j = 0; j < 4; j++) {
            int dd = ty + j * 8;
            dst[(size_t)(d0 + dd) * n + r] = t[tx][dd];
        }
    }
}

// ---------------- helpers ----------------------------------------------------
__device__ __forceinline__ unsigned smem_u32(const void* p)
{
    return (unsigned)__cvta_generic_to_shared(p);
}
__device__ __forceinline__ void mbar_init(unsigned mb, int count)
{
    asm volatile("mbarrier.init.shared.b64 [%0], %1;" :: "r"(mb), "r"(count) : "memory");
}
__device__ __forceinline__ void mbar_expect_tx(unsigned mb, unsigned bytes)
{
    asm volatile("mbarrier.arrive.expect_tx.shared.b64 _, [%0], %1;"
                 :: "r"(mb), "r"(bytes) : "memory");
}
__device__ __forceinline__ void mbar_wait(unsigned mb, int phase)
{
    asm volatile(
        "{\n\t"
        ".reg .pred P;\n\t"
        "W_%=:\n\t"
        "mbarrier.try_wait.parity.acquire.cta.shared::cta.b64 P, [%0], %1, 0x989680;\n\t"
        "@P bra D_%=;\n\t"
        "bra W_%=;\n\t"
        "D_%=:\n\t"
        "}"
        :: "r"(mb), "r"(phase) : "memory");
}
__device__ __forceinline__ void bulk_cp(unsigned smem_dst, const void* gmem_src,
                                        unsigned bytes, unsigned mb)
{
    asm volatile(
        "cp.async.bulk.shared::cluster.global.mbarrier::complete_tx::bytes [%0], [%1], %2, [%3];"
        :: "r"(smem_dst), "l"(gmem_src), "r"(bytes), "r"(mb) : "memory");
}
__device__ __forceinline__ void ldsm_x4(unsigned& r0, unsigned& r1,
                                        unsigned& r2, unsigned& r3, unsigned addr)
{
    asm volatile("ldmatrix.sync.aligned.m8n8.x4.shared.b16 {%0,%1,%2,%3}, [%4];"
                 : "=r"(r0), "=r"(r1), "=r"(r2), "=r"(r3) : "r"(addr));
}
__device__ __forceinline__ void mma_tf32(
    float& c0, float& c1, float& c2, float& c3,
    unsigned a0, unsigned a1, unsigned a2, unsigned a3,
    unsigned b0, unsigned b1)
{
    asm volatile(
        "mma.sync.aligned.m16n8k8.row.col.f32.tf32.tf32.f32 "
        "{%0,%1,%2,%3}, {%4,%5,%6,%7}, {%8,%9}, {%0,%1,%2,%3};\n"
        : "+f"(c0), "+f"(c1), "+f"(c2), "+f"(c3)
        : "r"(a0), "r"(a1), "r"(a2), "r"(a3), "r"(b0), "r"(b1));
}
__device__ __forceinline__ void mma_f16(
    float& c0, float& c1, float& c2, float& c3,
    unsigned a0, unsigned a1, unsigned a2, unsigned a3,
    unsigned b0, unsigned b1)
{
    asm volatile(
        "mma.sync.aligned.m16n8k16.row.col.f32.f16.f16.f32 "
        "{%0,%1,%2,%3}, {%4,%5,%6,%7}, {%8,%9}, {%0,%1,%2,%3};\n"
        : "+f"(c0), "+f"(c1), "+f"(c2), "+f"(c3)
        : "r"(a0), "r"(a1), "r"(a2), "r"(a3), "r"(b0), "r"(b1));
}
__device__ __forceinline__ void split_h(float x, __half& h, __half& l)
{
    h = __float2half_rn(x);
    l = __float2half_rn(x - __half2float(h));
}

// ---------------- propagation GEMM (R9 config — best measured) --------------
#define BM 128
#define BKK 64
#define ASTR 68
#define XSTR 68
#define A_SZ (BM * ASTR)
#define X_SZ (D * XSTR)
#define STG (A_SZ + X_SZ)
#define G_SMEM_BYTES (2 * STG * 4)

#define RT0 63
#define RT12 33
#define KS0 16
#define KS12 8
#define KPS0 8
#define KPS12 9
#define NB0 (RT0 * KS0)        // 1008
#define NB12 (RT12 * KS12)     // 264
#define NBLK (NB0 + 2 * NB12)  // 1536

__device__ __forceinline__ void issue_stage(
    float* Abuf, float* Xbuf, unsigned mb,
    const float* __restrict__ A, const float* __restrict__ XT,
    int n, int rowBase, int k0, int kEnd, int tid)
{
    const int kChunk = min(BKK, kEnd - k0);
    const unsigned kBytes = (unsigned)kChunk * 4u;
    if (tid == 0) {
        int nA = min(BM, n - rowBase);
        mbar_expect_tx(mb, (unsigned)nA * kBytes + (unsigned)D * kBytes);
    }
    {
        int gr = rowBase + tid;
        if (gr < n)
            bulk_cp(smem_u32(Abuf + tid * ASTR), A + (size_t)gr * n + k0, kBytes, mb);
    }
    if (tid < D)
        bulk_cp(smem_u32(Xbuf + tid * XSTR), XT + (size_t)tid * n + k0, kBytes, mb);
}

extern "C" __global__ void __launch_bounds__(128, 2)
gemm_all(const float* __restrict__ A0, const float* __restrict__ A1,
         const float* __restrict__ A2,
         const float* __restrict__ XT0, const float* __restrict__ XT1,
         const float* __restrict__ XT2,
         float* __restrict__ R0, float* __restrict__ R1, float* __restrict__ R2,
         float* __restrict__ degAll)
{
    extern __shared__ float dyn[];
    __shared__ uint64_t mbar[2];

    float* AbufS[2] = { dyn,        dyn + STG };
    float* XbufS[2] = { dyn + A_SZ, dyn + STG + A_SZ };

    const int tid  = threadIdx.x;
    const int lane = tid & 31;
    const int warp = tid >> 5;
    const int rq   = lane >> 2;
    const int kc   = lane & 3;
    const int wrow = warp * 32;

    const unsigned aLaneOff =
        (unsigned)(((lane & 7) + ((lane >> 3) & 1) * 8 + wrow) * ASTR) * 4u
        + (unsigned)(lane >> 4) * 16u;
    const unsigned xLaneOff =
        (unsigned)(((lane & 7) + (lane >> 4) * 8) * XSTR) * 4u
        + (unsigned)((lane >> 3) & 1) * 16u;

    // ---- map block -> (problem, rowTile, ksplit) ----
    const float *A, *XT; float *R, *deg;
    int n, kIters, kps, rowTile, split;
    int b = blockIdx.x;
    if (b < NB0) {
        A = A0; XT = XT0; R = R0; deg = degAll; n = NUP; kIters = 125; kps = KPS0;
        rowTile = b % RT0; split = b / RT0;
    } else {
        int idx = b - NB0;
        if (idx < NB12) { A = A1; XT = XT1; R = R1; deg = degAll + NUP;       n = NGU; }
        else            { A = A2; XT = XT2; R = R2; deg = degAll + NUP + NGU; n = NGP; idx -= NB12; }
        kIters = 66; kps = KPS12;
        rowTile = idx % RT12; split = idx / RT12;
    }

    const int rowBase = rowTile * BM;
    const int itStart = split * kps;
    const int itEnd   = min(kIters, itStart + kps);
    const int nIt     = itEnd - itStart;
    if (nIt <= 0) return;
    const int kEnd = min(n, itEnd * BKK);

    if (tid == 0) { mbar_init(smem_u32(&mbar[0]), 1); mbar_init(smem_u32(&mbar[1]), 1); }
    __syncthreads();

    issue_stage(AbufS[0], XbufS[0], smem_u32(&mbar[0]), A, XT, n, rowBase,
                itStart * BKK, kEnd, tid);

    float c0[8][4], c1[8][4];
    #pragma unroll
    for (int nt = 0; nt < 8; nt++)
        #pragma unroll
        for (int j = 0; j < 4; j++) { c0[nt][j] = 0.f; c1[nt][j] = 0.f; }
    float dacc[2][2] = {{0.f, 0.f}, {0.f, 0.f}};

    const int r00 = rowBase + wrow + rq;
    const int r10 = r00 + 16;
    int ph0 = 0, ph1 = 0;

    for (int i = 0; i < nIt; i++) {
        const int cur = i & 1;
        const int k0  = (itStart + i) * BKK;

        if (i + 1 < nIt)
            issue_stage(AbufS[cur ^ 1], XbufS[cur ^ 1], smem_u32(&mbar[cur ^ 1]),
                        A, XT, n, rowBase, k0 + BKK, kEnd, tid);

        if (cur == 0) { mbar_wait(smem_u32(&mbar[0]), ph0); ph0 ^= 1; }
        else          { mbar_wait(smem_u32(&mbar[1]), ph1); ph1 ^= 1; }

        const unsigned aBase = smem_u32(AbufS[cur]) + aLaneOff;
        const unsigned xBase = smem_u32(XbufS[cur]) + xLaneOff;
        const int kSteps = min(BKK, kEnd - k0) >> 3;

        #pragma unroll 8
        for (int ks = 0; ks < kSteps; ks++) {
            const unsigned kbB = (unsigned)(ks * 8) * 4u;
            unsigned a0[4], a1[4];
            ldsm_x4(a0[0], a0[1], a0[2], a0[3], aBase + kbB);
            ldsm_x4(a1[0], a1[1], a1[2], a1[3], aBase + 16u * ASTR * 4u + kbB);
            dacc[0][0] += __uint_as_float(a0[0]) + __uint_as_float(a0[2]);
            dacc[0][1] += __uint_as_float(a0[1]) + __uint_as_float(a0[3]);
            dacc[1][0] += __uint_as_float(a1[0]) + __uint_as_float(a1[2]);
            dacc[1][1] += __uint_as_float(a1[1]) + __uint_as_float(a1[3]);
            #pragma unroll
            for (int p = 0; p < 4; p++) {
                unsigned bx0, bx1, bx2, bx3;
                ldsm_x4(bx0, bx1, bx2, bx3, xBase + (unsigned)(p * 16 * XSTR) * 4u + kbB);
                mma_tf32(c0[2*p][0], c0[2*p][1], c0[2*p][2], c0[2*p][3],
                         a0[0], a0[1], a0[2], a0[3], bx0, bx1);
                mma_tf32(c0[2*p+1][0], c0[2*p+1][1], c0[2*p+1][2], c0[2*p+1][3],
                         a0[0], a0[1], a0[2], a0[3], bx2, bx3);
                mma_tf32(c1[2*p][0], c1[2*p][1], c1[2*p][2], c1[2*p][3],
                         a1[0], a1[1], a1[2], a1[3], bx0, bx1);
                mma_tf32(c1[2*p+1][0], c1[2*p+1][1], c1[2*p+1][2], c1[2*p+1][3],
                         a1[0], a1[1], a1[2], a1[3], bx2, bx3);
            }
        }
        __syncthreads();
    }

    // ---- deg: reduce over the 4 kc lanes, one atomic per row ----
    #pragma unroll
    for (int mt = 0; mt < 2; mt++) {
        float v0 = dacc[mt][0], v1 = dacc[mt][1];
        v0 += __shfl_xor_sync(0xffffffffu, v0, 1);
        v0 += __shfl_xor_sync(0xffffffffu, v0, 2);
        v1 += __shfl_xor_sync(0xffffffffu, v1, 1);
        v1 += __shfl_xor_sync(0xffffffffu, v1, 2);
        int r = (mt == 0) ? r00 : r10;
        if (kc == 0) {
            if (r < n)     atomicAdd(&deg[r], v0);
            if (r + 8 < n) atomicAdd(&deg[r + 8], v1);
        }
    }

    // ---- accumulate split-K partials ----
    const int ccBase = kc * 2;
    #pragma unroll
    for (int mt = 0; mt < 2; mt++) {
        const int r = (mt == 0) ? r00 : r10;
        float (*cc)[4] = (mt == 0) ? c0 : c1;
        #pragma unroll
        for (int nt = 0; nt < 8; nt++) {
            int col = nt * 8 + ccBase;
            if (r < n) {
                atomicAdd(&R[r * D + col],     cc[nt][0]);
                atomicAdd(&R[r * D + col + 1], cc[nt][1]);
            }
            if (r + 8 < n) {
                atomicAdd(&R[(r + 8) * D + col],     cc[nt][2]);
                atomicAdd(&R[(r + 8) * D + col + 1], cc[nt][3]);
            }
        }
    }
}

// ---------------- post: fp16 split build + uf/q, one launch -----------------
#define EPB ((P_N * (D / 4) + 255) / 256)   // 250
#define UFB (B_N / 4)                       // 128

__global__ void __launch_bounds__(256)
post_all(const float4* __restrict__ pe4,
         const float* __restrict__ ue,
         const int* __restrict__ uids,
         const float* __restrict__ W,
         float* __restrict__ out_uf)
{
    int b = blockIdx.x;
    if (b < EPB) {
        int i4 = b * 256 + threadIdx.x;          // float4 index over P_N*16
        if (i4 >= P_N * (D / 4)) return;
        int pr = i4 >> 4;
        float d0 = fmaxf(g_deg[U_N + pr], 1e-8f);
        float d1 = fmaxf(g_deg[NUP + NGU + G_N + pr], 1e-8f);
        float4 x  = pe4[i4];
        float4 r0 = reinterpret_cast<const float4*>(g_Rup)[U_N * (D / 4) + i4];
        float4 r1 = reinterpret_cast<const float4*>(g_Rgp)[G_N * (D / 4) + i4];
        float i0[4], i1[4];
        i0[0] = (x.x + r0.x / d0) * 0.5f;  i1[0] = (x.x + r1.x / d1) * 0.5f;
        i0[1] = (x.y + r0.y / d0) * 0.5f;  i1[1] = (x.y + r1.y / d1) * 0.5f;
        i0[2] = (x.z + r0.z / d0) * 0.5f;  i1[2] = (x.z + r1.z / d1) * 0.5f;
        i0[3] = (x.w + r0.w / d0) * 0.5f;  i1[3] = (x.w + r1.w / d1) * 0.5f;
        __align__(8) __half dh[4], dl[4], oh[4], ol[4];
        #pragma unroll
        for (int j = 0; j < 4; j++) {
            split_h(i0[j] - i1[j], dh[j], dl[j]);
            split_h(i1[j],         oh[j], ol[j]);
        }
        size_t o = (size_t)i4 * 4;
        *reinterpret_cast<uint2*>(&g_IDh[o]) = *reinterpret_cast<uint2*>(dh);
        *reinterpret_cast<uint2*>(&g_IDl[o]) = *reinterpret_cast<uint2*>(dl);
        *reinterpret_cast<uint2*>(&g_I1h[o]) = *reinterpret_cast<uint2*>(oh);
        *reinterpret_cast<uint2*>(&g_I1l[o]) = *reinterpret_cast<uint2*>(ol);
        return;
    }
    // ---- uf/q path (from accumulators) ----
    __shared__ float sh[4][D];
    int u  = threadIdx.x >> 6;
    int d  = threadIdx.x & 63;
    int bb = (b - EPB) * 4 + u;
    int uid = uids[bb];
    float dUp = fmaxf(g_deg[uid], 1e-8f);
    float dGu = fmaxf(g_deg[NUP + G_N + uid], 1e-8f);
    float x   = ue[(size_t)uid * D + d];
    float aUp = g_Rup[(size_t)uid * D + d];
    float aGu = g_Rgu[(size_t)(G_N + uid) * D + d];
    float v = 0.5f * ((x + aUp / dUp) * 0.5f + (x + aGu / dGu) * 0.5f);
    sh[u][d] = v;
    out_uf[bb * D + d] = v;
    __half h, l;
    split_h(v, h, l);
    g_Uh[bb * D + d] = h;
    g_Ul[bb * D + d] = l;
    __syncthreads();
    float acc = 0.f;
    #pragma unroll
    for (int k = 0; k < D; k++) acc += sh[u][k] * W[k * D + d];
    g_Qh[bb * D + d] = __float2half_rn(acc);
}

// ---------------- score kernel: fp16-pair MMA, splits precomputed -----------
// z  = qh·idh ; dd = uh·idh + uh·idl ; d1 = uh·i1h + uh·i1l + ul·i1h
// out = d1 + sigmoid(z/8)·dd
#define SSTH 72                                   // halfs per smem row (144 B)
#define HARR (64 * SSTH)                          // halfs per array
#define S_SMEM_BYTES (7 * HARR * 2)               // 64512 B

extern "C" __global__ void __launch_bounds__(256, 2)
score_all(float* __restrict__ scores)
{
    extern __shared__ __half hsm[];
    __half* Qh  = hsm;
    __half* Uh  = hsm + 1 * HARR;
    __half* Ul  = hsm + 2 * HARR;
    __half* IDh = hsm + 3 * HARR;
    __half* IDl = hsm + 4 * HARR;
    __half* I1h = hsm + 5 * HARR;
    __half* I1l = hsm + 6 * HARR;

    const int tid   = threadIdx.x;
    const int lane  = tid & 31;
    const int warp  = tid >> 5;
    const int warpB = warp >> 1;     // 4 groups of 16 users
    const int warpP = warp & 1;      // 2 groups of 32 papers
    const int rq    = lane >> 2;
    const int kc    = lane & 3;
    const int ub    = blockIdx.y * 64;
    const int pb    = blockIdx.x * 64;

    // ---- prologue: pure fp16 copies, uint4 = 8 halfs per slot ----
    {
        const __half* usrc[3] = { g_Qh, g_Uh, g_Ul };
        __half*       udst[3] = { Qh, Uh, Ul };
        #pragma unroll
        for (int a = 0; a < 3; a++)
            #pragma unroll
            for (int it = 0; it < 2; it++) {
                int slot = tid + it * 256;          // 512 slots
                int r  = slot >> 3;
                int c8 = (slot & 7) * 8;
                *reinterpret_cast<uint4*>(&udst[a][r * SSTH + c8]) =
                    *reinterpret_cast<const uint4*>(&usrc[a][(size_t)(ub + r) * D + c8]);
            }
        const __half* psrc[4] = { g_IDh, g_IDl, g_I1h, g_I1l };
        __half*       pdst[4] = { IDh, IDl, I1h, I1l };
        #pragma unroll
        for (int a = 0; a < 4; a++)
            #pragma unroll
            for (int it = 0; it < 2; it++) {
                int slot = tid + it * 256;
                int r  = slot >> 3;
                int c8 = (slot & 7) * 8;
                int gp = pb + r;
                uint4 v = make_uint4(0u, 0u, 0u, 0u);
                if (gp < P_N)
                    v = *reinterpret_cast<const uint4*>(&psrc[a][(size_t)gp * D + c8]);
                *reinterpret_cast<uint4*>(&pdst[a][r * SSTH + c8]) = v;
            }
    }
    __syncthreads();

    float z[4][4] = {}, dd[4][4] = {}, d1[4][4] = {};

    const unsigned aOff =
        (unsigned)(((lane & 7) + ((lane >> 3) & 1) * 8 + warpB * 16) * SSTH) * 2u
        + (unsigned)(lane >> 4) * 16u;
    const unsigned bOffBase =
        (unsigned)(((lane & 7) + ((lane >> 3) & 1) * 8 + warpP * 32) * SSTH) * 2u
        + (unsigned)(lane >> 4) * 16u;

    const unsigned qhB  = smem_u32(Qh)  + aOff;
    const unsigned uhB  = smem_u32(Uh)  + aOff;
    const unsigned ulB  = smem_u32(Ul)  + aOff;
    const unsigned idhB = smem_u32(IDh) + bOffBase;
    const unsigned idlB = smem_u32(IDl) + bOffBase;
    const unsigned i1hB = smem_u32(I1h) + bOffBase;
    const unsigned i1lB = smem_u32(I1l) + bOffBase;

    #pragma unroll
    for (int ks = 0; ks < 4; ks++) {          // k16 steps over D=64
        const unsigned kb = (unsigned)(ks * 32);   // 16 halfs = 32 B
        unsigned qh[4], uh[4], ul[4];
        ldsm_x4(qh[0], qh[1], qh[2], qh[3], qhB + kb);
        ldsm_x4(uh[0], uh[1], uh[2], uh[3], uhB + kb);
        ldsm_x4(ul[0], ul[1], ul[2], ul[3], ulB + kb);

        #pragma unroll
        for (int p = 0; p < 2; p++) {          // paper pairs: nt = 2p, 2p+1
            const unsigned po = (unsigned)(p * 16 * SSTH) * 2u + kb;
            unsigned dh0, dh1, dh2, dh3, dl0, dl1, dl2, dl3;
            unsigned oh0, oh1, oh2, oh3, ol0, ol1, ol2, ol3;
            ldsm_x4(dh0, dh1, dh2, dh3, idhB + po);
            ldsm_x4(dl0, dl1, dl2, dl3, idlB + po);
            ldsm_x4(oh0, oh1, oh2, oh3, i1hB + po);
            ldsm_x4(ol0, ol1, ol2, ol3, i1lB + po);

            mma_f16(z[2*p][0], z[2*p][1], z[2*p][2], z[2*p][3],
                    qh[0], qh[1], qh[2], qh[3], dh0, dh2);
            mma_f16(dd[2*p][0], dd[2*p][1], dd[2*p][2], dd[2*p][3],
                    uh[0], uh[1], uh[2], uh[3], dh0, dh2);
            mma_f16(dd[2*p][0], dd[2*p][1], dd[2*p][2], dd[2*p][3],
                    uh[0], uh[1], uh[2], uh[3], dl0, dl2);
            mma_f16(d1[2*p][0], d1[2*p][1], d1[2*p][2], d1[2*p][3],
                    uh[0], uh[1], uh[2], uh[3], oh0, oh2);
            mma_f16(d1[2*p][0], d1[2*p][1], d1[2*p][2], d1[2*p][3],
                    uh[0], uh[1], uh[2], uh[3], ol0, ol2);
            mma_f16(d1[2*p][0], d1[2*p][1], d1[2*p][2], d1[2*p][3],
                    ul[0], ul[1], ul[2], ul[3], oh0, oh2);

            mma_f16(z[2*p+1][0], z[2*p+1][1], z[2*p+1][2], z[2*p+1][3],
                    qh[0], qh[1], qh[2], qh[3], dh1, dh3);
            mma_f16(dd[2*p+1][0], dd[2*p+1][1], dd[2*p+1][2], dd[2*p+1][3],
                    uh[0], uh[1], uh[2], uh[3], dh1, dh3);
            mma_f16(dd[2*p+1][0], dd[2*p+1][1], dd[2*p+1][2], dd[2*p+1][3],
                    uh[0], uh[1], uh[2], uh[3], dl1, dl3);
            mma_f16(d1[2*p+1][0], d1[2*p+1][1], d1[2*p+1][2], d1[2*p+1][3],
                    uh[0], uh[1], uh[2], uh[3], oh1, oh3);
            mma_f16(d1[2*p+1][0], d1[2*p+1][1], d1[2*p+1][2], d1[2*p+1][3],
                    uh[0], uh[1], uh[2], uh[3], ol1, ol3);
            mma_f16(d1[2*p+1][0], d1[2*p+1][1], d1[2*p+1][2], d1[2*p+1][3],
                    ul[0], ul[1], ul[2], ul[3], oh1, oh3);
        }
    }

    const float scale = 0.125f;   // 1/sqrt(64)
    #pragma unroll
    for (int nt = 0; nt < 4; nt++) {
        #pragma unroll
        for (int j = 0; j < 4; j++) {
            int r = ub + warpB * 16 + rq + ((j >= 2) ? 8 : 0);
            int p = pb + warpP * 32 + nt * 8 + kc * 2 + (j & 1);
            if (p < P_N) {
                float a0 = 1.f / (1.f + __expf(-z[nt][j] * scale));
                scores[(size_t)r * P_N + p] = d1[nt][j] + a0 * dd[nt][j];
            }
        }
    }
}

// ---------------- launch -----------------------------------------------------
extern "C" void kernel_launch(void* const* d_in, const int* in_sizes, int n_in,
                              void* d_out, int out_size)
{
    const float* A_up = (const float*)d_in[0];
    const float* A_gu = (const float*)d_in[1];
    const float* A_gp = (const float*)d_in[2];
    const float* ue   = (const float*)d_in[3];
    const float* pe   = (const float*)d_in[4];
    const float* ge   = (const float*)d_in[5];
    const float* W    = (const float*)d_in[6];
    const int*   uids = (const int*)d_in[7];
    float* out = (float*)d_out;

    float *pXT0, *pXT1, *pXT2, *pRup, *pRgu, *pRgp, *pdeg;
    cudaGetSymbolAddress((void**)&pXT0, g_XT0);
    cudaGetSymbolAddress((void**)&pXT1, g_XT1);
    cudaGetSymbolAddress((void**)&pXT2, g_XT2);
    cudaGetSymbolAddress((void**)&pRup, g_Rup);
    cudaGetSymbolAddress((void**)&pRgu, g_Rgu);
    cudaGetSymbolAddress((void**)&pRgp, g_Rgp);
    cudaGetSymbolAddress((void**)&pdeg, g_deg);

    cudaFuncSetAttribute(gemm_all,  cudaFuncAttributeMaxDynamicSharedMemorySize, G_SMEM_BYTES);
    cudaFuncSetAttribute(score_all, cudaFuncAttributeMaxDynamicSharedMemorySize, S_SMEM_BYTES);

    init_and_transpose<<<TPALL + ZBLK, 256>>>(ue, pe, ge);

    gemm_all<<<NBLK, 128, G_SMEM_BYTES>>>(A_up, A_gu, A_gp,
                                          pXT0, pXT1, pXT2,
                                          pRup, pRgu, pRgp, pdeg);

    post_all<<<EPB + UFB, 256>>>((const float4*)pe, ue, uids, W,
                                 out + (size_t)B_N * P_N);

    dim3 sg((P_N + 63) / 64, B_N / 64);
    score_all<<<sg, 256, S_SMEM_BYTES>>>(out);
}